// round 12
// baseline (speedup 1.0000x reference)
#include <cuda_runtime.h>
#include <cuda_bf16.h>
#include <cuda_fp16.h>
#include <cstdint>

#define MAXN 100000
#define MAXE 500000

// ------------------------- scratch (device globals, no mallocs) -------------
__device__ __align__(16) __half g_Ps16[(size_t)MAXN * 256]; // src proj fp16
__device__ __align__(16) __half g_Pt16[(size_t)MAXN * 256]; // dst proj fp16 (+bias)
__device__ __align__(16) __half g_emb16[(size_t)MAXN * 128];
// bf16 hi/lo pre-split emb (padded 128 rows for in-bounds tile reads)
__device__ __align__(16) __nv_bfloat16 g_embH[(size_t)(MAXN + 128) * 128];
__device__ __align__(16) __nv_bfloat16 g_embL[(size_t)(MAXN + 128) * 128];
// aggregates padded 128 rows: tail-tile cp.async reads stay in-bounds (padding
// is zero-initialized and never written -> harmless zeros)
__device__ __align__(16) float g_attn0[(size_t)(MAXN + 128) * 128];
__device__ __align__(16) float g_attn1[(size_t)(MAXN + 128) * 128];
__device__ __align__(16) float g_mean[(size_t)(MAXN + 128) * 128];
__device__ float g_cnt[MAXN];
__device__ float g_sum0[MAXN], g_sum1[MAXN];
__device__ float g_bias[256];                // [bae | bar]
__device__ float g_wv[256];                  // [w0w | w1w]
// bf16 weight tiles, layout [tile][khalf][n][64] (B^T, hi/lo split)
__device__ __align__(16) __nv_bfloat16 g_BpreH[4 * 16384];
__device__ __align__(16) __nv_bfloat16 g_BpreL[4 * 16384];
__device__ __align__(16) __nv_bfloat16 g_BoutH[3 * 16384];
__device__ __align__(16) __nv_bfloat16 g_BoutL[3 * 16384];

// ------------------------- PTX helpers --------------------------------------
__device__ __forceinline__ uint32_t smem_u32(const void* p) {
    uint32_t a;
    asm("{ .reg .u64 t; cvta.to.shared.u64 t, %1; cvt.u32.u64 %0, t; }" : "=r"(a) : "l"(p));
    return a;
}

#define LDM_X4(r, addr) \
    asm volatile("ldmatrix.sync.aligned.m8n8.x4.shared.b16 {%0,%1,%2,%3}, [%4];" \
        : "=r"((r)[0]), "=r"((r)[1]), "=r"((r)[2]), "=r"((r)[3]) : "r"(addr))

#define LDM_X2(r, addr) \
    asm volatile("ldmatrix.sync.aligned.m8n8.x2.shared.b16 {%0,%1}, [%2];" \
        : "=r"((r)[0]), "=r"((r)[1]) : "r"(addr))

#define MMA_BF16(c, a, b) \
    asm volatile("mma.sync.aligned.m16n8k16.row.col.f32.bf16.bf16.f32 " \
        "{%0,%1,%2,%3}, {%4,%5,%6,%7}, {%8,%9}, {%0,%1,%2,%3};" \
        : "+f"((c)[0]), "+f"((c)[1]), "+f"((c)[2]), "+f"((c)[3]) \
        : "r"((a)[0]), "r"((a)[1]), "r"((a)[2]), "r"((a)[3]), "r"((b)[0]), "r"((b)[1]))

#define CP_ASYNC16(saddr, gptr) \
    asm volatile("cp.async.cg.shared.global [%0], [%1], 16;" \
        :: "r"(saddr), "l"(gptr) : "memory")
#define CP_COMMIT() asm volatile("cp.async.commit_group;" ::: "memory")
#define CP_WAIT0()  asm volatile("cp.async.wait_group 0;" ::: "memory")

__device__ __forceinline__ void red_add4(float* p, float a, float b, float c, float d) {
    asm volatile("red.global.add.v4.f32 [%0], {%1, %2, %3, %4};"
        :: "l"(p), "f"(a), "f"(b), "f"(c), "f"(d) : "memory");
}

// ------------------------- fast math ---------------------------------------
__device__ __forceinline__ float fast_tanh(float x) {
    float e;
    asm("ex2.approx.f32 %0, %1;" : "=f"(e) : "f"(x * 2.885390082f));
    float r;
    asm("rcp.approx.f32 %0, %1;" : "=f"(r) : "f"(e + 1.0f));
    return fmaf(-2.0f, r, 1.0f);
}

__device__ __forceinline__ float fast_exp(float x) {
    float e;
    asm("ex2.approx.f32 %0, %1;" : "=f"(e) : "f"(x * 1.4426950408889634f));
    return e;
}

// ------------------------- merged setup kernel ------------------------------
__global__ void setup_all(const float* __restrict__ emb, int N,
                          const float* __restrict__ Wae, const float* __restrict__ War,
                          const float* __restrict__ bae, const float* __restrict__ bar,
                          const float* __restrict__ w0w, const float* __restrict__ w1w,
                          const float* __restrict__ W1, const float* __restrict__ W2,
                          const float* __restrict__ W3) {
    int b = blockIdx.x;
    if (b < 2048) {
        size_t stride = (size_t)2048 * 256;
        size_t i = (size_t)b * 256 + threadIdx.x;
        size_t n4 = (size_t)N * 32;
        float4 z = make_float4(0.f, 0.f, 0.f, 0.f);
        float4* a4 = (float4*)g_attn0;
        float4* b4 = (float4*)g_attn1;
        float4* m4 = (float4*)g_mean;
        for (size_t j = i; j < n4; j += stride) { a4[j] = z; b4[j] = z; m4[j] = z; }
        for (size_t j = i; j < (size_t)N; j += stride) {
            g_cnt[j] = 0.f; g_sum0[j] = 0.f; g_sum1[j] = 0.f;
        }
    } else if (b < 4096) {
        size_t stride = (size_t)2048 * 256;
        size_t i = (size_t)(b - 2048) * 256 + threadIdx.x;
        int total2 = N * 64;
        __half2* d16 = (__half2*)g_emb16;
        __nv_bfloat162* dH = (__nv_bfloat162*)g_embH;
        __nv_bfloat162* dL = (__nv_bfloat162*)g_embL;
        const float2* src = (const float2*)emb;
        for (size_t j = i; j < (size_t)total2; j += stride) {
            float2 v = src[j];
            __nv_bfloat162 h = __floats2bfloat162_rn(v.x, v.y);
            __nv_bfloat162 l = __floats2bfloat162_rn(v.x - __bfloat162float(h.x),
                                                     v.y - __bfloat162float(h.y));
            dH[j] = h;
            dL[j] = l;
            d16[j] = __floats2half2_rn(v.x, v.y);
        }
    } else {
        int i = (b - 4096) * 256 + threadIdx.x;
        if (i < 65536) {
            int y = i >> 14, r = i & 16383, k = r >> 7, n = r & 127;
            int cc = (y << 7) + n;
            float v;
            if (y == 0)      v = Wae[(128 + k) * 128 + cc];
            else if (y == 1) v = War[k * 128 + (cc - 128)];
            else if (y == 2) v = Wae[k * 128 + (cc - 256)];
            else             v = War[(128 + k) * 128 + (cc - 384)];
            __nv_bfloat16 h = __float2bfloat16(v);
            __nv_bfloat16 l = __float2bfloat16(v - __bfloat162float(h));
            int kh = k >> 6, kk = k & 63;
            size_t off = (size_t)y * 16384 + kh * 8192 + n * 64 + kk;
            g_BpreH[off] = h;
            g_BpreL[off] = l;
        } else if (i < 65536 + 49152) {
            int j = i - 65536;
            int t = j >> 14, r = j & 16383, k = r >> 7, n = r & 127;
            const float* W = (t == 0) ? W1 : (t == 1) ? W2 : W3;
            float v = W[k * 128 + n];
            __nv_bfloat16 h = __float2bfloat16(v);
            __nv_bfloat16 l = __float2bfloat16(v - __bfloat162float(h));
            int kh = k >> 6, kk = k & 63;
            size_t off = (size_t)t * 16384 + kh * 8192 + n * 64 + kk;
            g_BoutH[off] = h;
            g_BoutL[off] = l;
        }
        if (i < 128) {
            g_bias[i] = bae[i];  g_bias[128 + i] = bar[i];
            g_wv[i]   = w0w[i];  g_wv[128 + i]   = w1w[i];
        }
    }
}

// ------------------------- GEMM machinery -----------------------------------
// 128-row stage (73728 B): AH @0, AL @18432, BH @36864, BL @55296.
#define STG   73728u
#define SMEM_PRE (2 * STG)

// gemm_out stage (M=64 tile, 55296 B): AH @0, AL @9216, BH @18432, BL @36864.
#define OF32A  55296u                 // fp32 scratch A (64x64 = 16384 B)
#define OF32B  71680u                 // fp32 scratch B
#define OBIAS  88064u
#define SMEM_OUT (OBIAS + 1024u)

__device__ __forceinline__ uint32_t b2u(__nv_bfloat162 v) {
    return *reinterpret_cast<uint32_t*>(&v);
}

// cp.async copy of a 128x64 bf16 tile: 128 rows x 8 int4, dst stride 9 int4
__device__ __forceinline__ void cp_rows(uint32_t sbase, const int4* __restrict__ src,
                                        int srcStride4, int tid) {
#pragma unroll
    for (int i = 0; i < 4; i++) {
        int idx = tid + i * 256;
        int n = idx >> 3, q = idx & 7;
        CP_ASYNC16(sbase + (uint32_t)(n * 9 + q) * 16, src + (size_t)n * srcStride4 + q);
    }
}

// cp.async copy of a 64x64 bf16 tile: 64 rows x 8 int4
__device__ __forceinline__ void cp_rows64(uint32_t sbase, const int4* __restrict__ src,
                                          int srcStride4, int tid) {
#pragma unroll
    for (int i = 0; i < 2; i++) {
        int idx = tid + i * 256;
        int n = idx >> 3, q = idx & 7;
        CP_ASYNC16(sbase + (uint32_t)(n * 9 + q) * 16, src + (size_t)n * srcStride4 + q);
    }
}

// cp.async copy of a 64x64 fp32 half-tile into scratch (row*16+q float4s)
__device__ __forceinline__ void cp_f32_half64(uint32_t sbase, const float4* __restrict__ src,
                                              int kh, int tid) {
#pragma unroll
    for (int i = 0; i < 4; i++) {
        int idx = tid + i * 256;
        int row = idx >> 4, q = idx & 15;
        CP_ASYNC16(sbase + (uint32_t)(row * 16 + q) * 16,
                   src + (size_t)row * 32 + kh * 16 + q);
    }
}

__device__ __forceinline__ void split_store(__nv_bfloat16* sAh, __nv_bfloat16* sAl,
                                            int row, int q, float4 v) {
    __nv_bfloat162 h01 = __floats2bfloat162_rn(v.x, v.y);
    __nv_bfloat162 h23 = __floats2bfloat162_rn(v.z, v.w);
    __nv_bfloat162 l01 = __floats2bfloat162_rn(v.x - __bfloat162float(h01.x),
                                               v.y - __bfloat162float(h01.y));
    __nv_bfloat162 l23 = __floats2bfloat162_rn(v.z - __bfloat162float(h23.x),
                                               v.w - __bfloat162float(h23.y));
    *(uint2*)(sAh + row * 72 + q * 4) = make_uint2(b2u(h01), b2u(h23));
    *(uint2*)(sAl + row * 72 + q * 4) = make_uint2(b2u(l01), b2u(l23));
}

// 128-row warp-tile mma: acc[4][4][4]
__device__ __forceinline__ void mma_half(float acc[4][4][4], uint32_t base,
                                         int warp_m, int warp_n, int lane) {
    int arow = warp_m * 64 + (lane & 15);
    int acolB = (lane >> 4) * 16;
    int brow = warp_n * 32 + (lane & 7);
    int bcolB = ((lane >> 3) & 1) * 16;
    uint32_t aoff = base + 0u     + arow * 144 + acolB;
    uint32_t loff = base + 18432u + arow * 144 + acolB;
    uint32_t boff = base + 36864u + brow * 144 + bcolB;
    uint32_t moff = base + 55296u + brow * 144 + bcolB;

#pragma unroll
    for (int ks = 0; ks < 4; ks++) {
        uint32_t kbB = ks * 32;
        uint32_t ah[4][4], al[4][4], bh[4][2], bl[4][2];
#pragma unroll
        for (int mt = 0; mt < 4; mt++) {
            uint32_t off = mt * 16 * 144 + kbB;
            LDM_X4(ah[mt], aoff + off);
            LDM_X4(al[mt], loff + off);
        }
#pragma unroll
        for (int nt = 0; nt < 4; nt++) {
            uint32_t off = nt * 8 * 144 + kbB;
            LDM_X2(bh[nt], boff + off);
            LDM_X2(bl[nt], moff + off);
        }
#pragma unroll
        for (int mt = 0; mt < 4; mt++)
#pragma unroll
            for (int nt = 0; nt < 4; nt++) {
                MMA_BF16(acc[mt][nt], ah[mt], bh[nt]);
                MMA_BF16(acc[mt][nt], al[mt], bh[nt]);
                MMA_BF16(acc[mt][nt], ah[mt], bl[nt]);
            }
    }
}

// 64-row warp-tile mma (gemm_out): acc[2][4][4], warp tile 32x32
__device__ __forceinline__ void mma_half64(float acc[2][4][4], uint32_t base,
                                           int warp_m, int warp_n, int lane) {
    int arow = warp_m * 32 + (lane & 15);
    int acolB = (lane >> 4) * 16;
    int brow = warp_n * 32 + (lane & 7);
    int bcolB = ((lane >> 3) & 1) * 16;
    uint32_t aoff = base + 0u     + arow * 144 + acolB;
    uint32_t loff = base + 9216u  + arow * 144 + acolB;
    uint32_t boff = base + 18432u + brow * 144 + bcolB;
    uint32_t moff = base + 36864u + brow * 144 + bcolB;

#pragma unroll
    for (int ks = 0; ks < 4; ks++) {
        uint32_t kbB = ks * 32;
        uint32_t ah[2][4], al[2][4], bh[4][2], bl[4][2];
#pragma unroll
        for (int mt = 0; mt < 2; mt++) {
            uint32_t off = mt * 16 * 144 + kbB;
            LDM_X4(ah[mt], aoff + off);
            LDM_X4(al[mt], loff + off);
        }
#pragma unroll
        for (int nt = 0; nt < 4; nt++) {
            uint32_t off = nt * 8 * 144 + kbB;
            LDM_X2(bh[nt], boff + off);
            LDM_X2(bl[nt], moff + off);
        }
#pragma unroll
        for (int mt = 0; mt < 2; mt++)
#pragma unroll
            for (int nt = 0; nt < 4; nt++) {
                MMA_BF16(acc[mt][nt], ah[mt], bh[nt]);
                MMA_BF16(acc[mt][nt], al[mt], bh[nt]);
                MMA_BF16(acc[mt][nt], ah[mt], bl[nt]);
            }
    }
}

// ------------------------- pre-projection GEMM (pipelined, 1 CTA/SM) --------
__global__ __launch_bounds__(256) void gemm_pre_mma(int M) {
    extern __shared__ char smc[];
    uint32_t sb = smem_u32(smc);
    int tid = threadIdx.x, lane = tid & 31, wid = tid >> 5;
    int rowBase = blockIdx.x * 128, yt = blockIdx.y;
    int warp_m = wid & 1, warp_n = wid >> 1;
    int grp = lane >> 2, qid = lane & 3;

    float acc[4][4][4];
#pragma unroll
    for (int mt = 0; mt < 4; mt++)
#pragma unroll
        for (int nt = 0; nt < 4; nt++)
#pragma unroll
            for (int j = 0; j < 4; j++) acc[mt][nt][j] = 0.f;

    cp_rows(sb + 0u,      (const int4*)g_embH + (size_t)rowBase * 16, 16, tid);
    cp_rows(sb + 18432u,  (const int4*)g_embL + (size_t)rowBase * 16, 16, tid);
    cp_rows(sb + 36864u,  (const int4*)(g_BpreH + (size_t)yt * 16384), 8, tid);
    cp_rows(sb + 55296u,  (const int4*)(g_BpreL + (size_t)yt * 16384), 8, tid);
    CP_COMMIT();

#pragma unroll 1
    for (int kh = 0; kh < 2; kh++) {
        CP_WAIT0();
        __syncthreads();
        if (kh == 0) {
            cp_rows(sb + STG + 0u,     (const int4*)g_embH + (size_t)rowBase * 16 + 8, 16, tid);
            cp_rows(sb + STG + 18432u, (const int4*)g_embL + (size_t)rowBase * 16 + 8, 16, tid);
            cp_rows(sb + STG + 36864u, (const int4*)(g_BpreH + (size_t)yt * 16384 + 8192), 8, tid);
            cp_rows(sb + STG + 55296u, (const int4*)(g_BpreL + (size_t)yt * 16384 + 8192), 8, tid);
            CP_COMMIT();
        }
        mma_half(acc, sb + (uint32_t)kh * STG, warp_m, warp_n, lane);
    }

    __half* Cbase;
    int colOff;
    if (yt < 2) { Cbase = g_Ps16; colOff = yt * 128; }
    else        { Cbase = g_Pt16; colOff = (yt - 2) * 128; }
    bool addBias = (yt >= 2);
#pragma unroll
    for (int mt = 0; mt < 4; mt++) {
#pragma unroll
        for (int nt = 0; nt < 4; nt++) {
            int c = colOff + warp_n * 32 + nt * 8 + qid * 2;
            float b0 = 0.f, b1 = 0.f;
            if (addBias) { b0 = g_bias[c]; b1 = g_bias[c + 1]; }
            int r0 = rowBase + warp_m * 64 + mt * 16 + grp;
            if (r0 < M)
                *(__half2*)(Cbase + (size_t)r0 * 256 + c) =
                    __floats2half2_rn(acc[mt][nt][0] + b0, acc[mt][nt][1] + b1);
            int r1 = r0 + 8;
            if (r1 < M)
                *(__half2*)(Cbase + (size_t)r1 * 256 + c) =
                    __floats2half2_rn(acc[mt][nt][2] + b0, acc[mt][nt][3] + b1);
        }
    }
}

// ------------------------- emb@W1 term GEMM (runs on side stream) -----------
// out = tanh(emb @ W1 + b1), fp32 output. Same pipelined structure as gemm_pre.
__global__ __launch_bounds__(256) void gemm_w1_mma(const float* __restrict__ b1,
                                                   float* __restrict__ out, int M) {
    extern __shared__ char smc[];
    uint32_t sb = smem_u32(smc);
    int tid = threadIdx.x, lane = tid & 31, wid = tid >> 5;
    int rowBase = blockIdx.x * 128;
    int warp_m = wid & 1, warp_n = wid >> 1;
    int grp = lane >> 2, qid = lane & 3;

    float acc[4][4][4];
#pragma unroll
    for (int mt = 0; mt < 4; mt++)
#pragma unroll
        for (int nt = 0; nt < 4; nt++)
#pragma unroll
            for (int j = 0; j < 4; j++) acc[mt][nt][j] = 0.f;

    cp_rows(sb + 0u,      (const int4*)g_embH + (size_t)rowBase * 16, 16, tid);
    cp_rows(sb + 18432u,  (const int4*)g_embL + (size_t)rowBase * 16, 16, tid);
    cp_rows(sb + 36864u,  (const int4*)g_BoutH, 8, tid);
    cp_rows(sb + 55296u,  (const int4*)g_BoutL, 8, tid);
    CP_COMMIT();

#pragma unroll 1
    for (int kh = 0; kh < 2; kh++) {
        CP_WAIT0();
        __syncthreads();
        if (kh == 0) {
            cp_rows(sb + STG + 0u,     (const int4*)g_embH + (size_t)rowBase * 16 + 8, 16, tid);
            cp_rows(sb + STG + 18432u, (const int4*)g_embL + (size_t)rowBase * 16 + 8, 16, tid);
            cp_rows(sb + STG + 36864u, (const int4*)(g_BoutH + 8192), 8, tid);
            cp_rows(sb + STG + 55296u, (const int4*)(g_BoutL + 8192), 8, tid);
            CP_COMMIT();
        }
        mma_half(acc, sb + (uint32_t)kh * STG, warp_m, warp_n, lane);
    }

#pragma unroll
    for (int mt = 0; mt < 4; mt++) {
#pragma unroll
        for (int nt = 0; nt < 4; nt++) {
            int c = warp_n * 32 + nt * 8 + qid * 2;
            float bv0 = __ldg(b1 + c), bv1 = __ldg(b1 + c + 1);
            int r0 = rowBase + warp_m * 64 + mt * 16 + grp;
            if (r0 < M)
                *(float2*)(out + (size_t)r0 * 128 + c) =
                    make_float2(fast_tanh(acc[mt][nt][0] + bv0),
                                fast_tanh(acc[mt][nt][1] + bv1));
            int r1 = r0 + 8;
            if (r1 < M)
                *(float2*)(out + (size_t)r1 * 128 + c) =
                    make_float2(fast_tanh(acc[mt][nt][2] + bv0),
                                fast_tanh(acc[mt][nt][3] + bv1));
        }
    }
}

// ------------------------- attention edge pass -------------------------------
__global__ void edge_attn(const int* __restrict__ er_src, const int* __restrict__ er_dst,
                          int Eer,
                          const float* __restrict__ w0b, const float* __restrict__ w1b) {
    int wid = threadIdx.x >> 5, lane = threadIdx.x & 31;
    int gw = blockIdx.x * 8 + wid;
    if (gw >= Eer) return;
    int s = er_src[gw], t = er_dst[gw];
    uint4 a = ((const uint4*)(g_Ps16 + (size_t)s * 256))[lane];
    uint4 b = ((const uint4*)(g_Pt16 + (size_t)t * 256))[lane];
    float4 w0 = ((const float4*)g_wv)[lane * 2];
    float4 w1 = ((const float4*)g_wv)[lane * 2 + 1];

    const __half2* ah = reinterpret_cast<const __half2*>(&a);
    const __half2* bh = reinterpret_cast<const __half2*>(&b);
    float part = 0.f;
    float wv[8] = {w0.x, w0.y, w0.z, w0.w, w1.x, w1.y, w1.z, w1.w};
#pragma unroll
    for (int j = 0; j < 4; j++) {
        float2 xa = __half22float2(ah[j]);
        float2 xb = __half22float2(bh[j]);
        part += fast_tanh(xa.x + xb.x) * wv[2 * j]
              + fast_tanh(xa.y + xb.y) * wv[2 * j + 1];
    }
#pragma unroll
    for (int o = 1; o <= 8; o <<= 1)
        part += __shfl_xor_sync(0xFFFFFFFFu, part, o);
    float other = __shfl_xor_sync(0xFFFFFFFFu, part, 16);

    float p0, p1;
    if (lane == 0) {
        p0 = fast_exp(part + w0b[0]);
        p1 = fast_exp(other + w1b[0]);
        atomicAdd(g_sum0 + s, p0);
        atomicAdd(g_sum1 + t, p1);
    }
    p0 = __shfl_sync(0xFFFFFFFFu, p0, 0);
    p1 = __shfl_sync(0xFFFFFFFFu, p1, 0);

    uint2 rv = ((const uint2*)(g_emb16 + (size_t)t * 128))[lane];
    const __half2* rh = reinterpret_cast<const __half2*>(&rv);
    float2 r01 = __half22float2(rh[0]);
    float2 r23 = __half22float2(rh[1]);
    red_add4(g_attn0 + (size_t)s * 128 + lane * 4,
             p0 * r01.x, p0 * r01.y, p0 * r23.x, p0 * r23.y);

    uint2 hv = ((const uint2*)(g_emb16 + (size_t)s * 128))[lane];
    const __half2* hh = reinterpret_cast<const __half2*>(&hv);
    float2 h01 = __half22float2(hh[0]);
    float2 h23 = __half22float2(hh[1]);
    red_add4(g_attn1 + (size_t)t * 128 + lane * 4,
             p1 * h01.x, p1 * h01.y, p1 * h23.x, p1 * h23.y);
}

// ------------------------- mean edge pass (runs on side stream) -------------
__global__ void mean_scatter(const int* __restrict__ ee_src, const int* __restrict__ ee_dst,
                             int Eee,
                             const int* __restrict__ rr_src, const int* __restrict__ rr_dst,
                             int Err) {
    int wid = threadIdx.x >> 5, lane = threadIdx.x & 31;
    int gw = blockIdx.x * 8 + wid;
    int total = Eee + Err;
    if (gw >= total) return;
    int s, t;
    if (gw < Eee) { s = ee_src[gw]; t = ee_dst[gw]; }
    else          { s = rr_src[gw - Eee]; t = rr_dst[gw - Eee]; }

    uint2 hv = ((const uint2*)(g_emb16 + (size_t)t * 128))[lane];
    const __half2* hh = reinterpret_cast<const __half2*>(&hv);
    float2 v01 = __half22float2(hh[0]);
    float2 v23 = __half22float2(hh[1]);
    red_add4(g_mean + (size_t)s * 128 + lane * 4, v01.x, v01.y, v23.x, v23.y);
    if (lane == 0) atomicAdd(g_cnt + s, 1.0f);
}

// ------------------------- output GEMM: attn + mean terms, out += -----------
// 4 stages s=(t,kh), t in {1,2}. Single bf16 stage buffer + fp32 smem scratch.
__global__ __launch_bounds__(256, 2) void gemm_out_mma(const float* __restrict__ b2,
                                                       const float* __restrict__ b3,
                                                       float* __restrict__ out, int M) {
    extern __shared__ char smc[];
    float* sbias = (float*)(smc + OBIAS);
    uint32_t sb = smem_u32(smc);
    int tid = threadIdx.x, lane = tid & 31, wid = tid >> 5;
    int rowBase = blockIdx.x * 64;
    int warp_m = wid & 1, warp_n = wid >> 1;
    int grp = lane >> 2, qid = lane & 3;

    if (tid < 128) {
        sbias[tid]       = b2[tid];
        sbias[128 + tid] = b3[tid];
    }

    float res[2][4][4], acc[2][4][4];
#pragma unroll
    for (int mt = 0; mt < 2; mt++)
#pragma unroll
        for (int nt = 0; nt < 4; nt++)
#pragma unroll
            for (int j = 0; j < 4; j++) { res[mt][nt][j] = 0.f; acc[mt][nt][j] = 0.f; }

    float ps0[4], ps1[4];
    int rbq = tid >> 4;   // thread's convert-slot base row (0..15)

    // prologue: stage 0 = (t=1, kh=0): B + fp32 scratch + ps
    cp_rows(sb + 18432u, (const int4*)(g_BoutH + 16384), 8, tid);
    cp_rows(sb + 36864u, (const int4*)(g_BoutL + 16384), 8, tid);
    cp_f32_half64(sb + OF32A, (const float4*)g_attn0 + (size_t)rowBase * 32, 0, tid);
    cp_f32_half64(sb + OF32B, (const float4*)g_attn1 + (size_t)rowBase * 32, 0, tid);
#pragma unroll
    for (int i = 0; i < 4; i++) {
        int gr = rowBase + rbq + i * 16;
        bool ok = gr < M;
        ps0[i] = ok ? g_sum0[gr] : 1.f;
        ps1[i] = ok ? g_sum1[gr] : 1.f;
    }
    CP_COMMIT();

#pragma unroll 1
    for (int s = 0; s < 4; s++) {
        int t = 1 + (s >> 1), kh = s & 1;
        int ns = s + 1;
        int nt = 1 + (ns >> 1), nkh = ns & 1;
        CP_WAIT0();
        __syncthreads();

        // convert scratch -> stage A (uses ps loaded for this stage)
        {
            __nv_bfloat16* cAh = (__nv_bfloat16*)smc;
            __nv_bfloat16* cAl = (__nv_bfloat16*)(smc + 9216);
#pragma unroll
            for (int i = 0; i < 4; i++) {
                int row = rbq + i * 16;
                int q = tid & 15;
                float4 v;
                if (t == 1) {
                    float4 v0 = *(const float4*)(smc + OF32A + (size_t)(row * 16 + q) * 16);
                    float4 v1 = *(const float4*)(smc + OF32B + (size_t)(row * 16 + q) * 16);
                    float i0 = __fdividef(1.0f, ps0[i] + 1e-9f);
                    float i1 = __fdividef(1.0f, ps1[i] + 1e-9f);
                    v.x = v0.x * i0 + v1.x * i1;
                    v.y = v0.y * i0 + v1.y * i1;
                    v.z = v0.z * i0 + v1.z * i1;
                    v.w = v0.w * i0 + v1.w * i1;
                } else {
                    float4 v0 = *(const float4*)(smc + OF32A + (size_t)(row * 16 + q) * 16);
                    float rc = 1.0f / fmaxf(ps0[i], 1.0f);
                    v.x = v0.x * rc; v.y = v0.y * rc;
                    v.z = v0.z * rc; v.w = v0.w * rc;
                }
                split_store(cAh, cAl, row, q, v);
            }
            __syncthreads();
        }

        // scratch prefetch for stage s+1 (scratch free now) — overlaps mma
        if (ns < 4) {
            if (nt == 1) {
                cp_f32_half64(sb + OF32A, (const float4*)g_attn0 + (size_t)rowBase * 32, nkh, tid);
                cp_f32_half64(sb + OF32B, (const float4*)g_attn1 + (size_t)rowBase * 32, nkh, tid);
                // ps unchanged for same term's second half (already loaded)
            } else {
                cp_f32_half64(sb + OF32A, (const float4*)g_mean + (size_t)rowBase * 32, nkh, tid);
                if (nkh == 0) {  // first mean stage: load cnt
#pragma unroll
                    for (int i = 0; i < 4; i++) {
                        int gr = rowBase + rbq + i * 16;
                        ps0[i] = (gr < M) ? g_cnt[gr] : 1.f;
                    }
                }
            }
            CP_COMMIT();
        }

        mma_half64(acc, sb, warp_m, warp_n, lane);
        __syncthreads();   // stage buffer free

        // B prefetch for stage s+1
        if (ns < 4) {
            cp_rows(sb + 18432u, (const int4*)(g_BoutH + (size_t)nt * 16384 + nkh * 8192), 8, tid);
            cp_rows(sb + 36864u, (const int4*)(g_BoutL + (size_t)nt * 16384 + nkh * 8192), 8, tid);
            CP_COMMIT();
        }

        if (kh == 1) {  // term epilogue
            const float* bias = sbias + (t - 1) * 128;
#pragma unroll
            for (int mt = 0; mt < 2; mt++)
#pragma unroll
                for (int nt2 = 0; nt2 < 4; nt2++) {
                    int c = warp_n * 32 + nt2 * 8 + qid * 2;
                    float bv0 = bias[c], bv1 = bias[c + 1];
                    res[mt][nt2][0] += fast_tanh(acc[mt][nt2][0] + bv0);
                    res[mt][nt2][1] += fast_tanh(acc[mt][nt2][1] + bv1);
                    res[mt][nt2][2] += fast_tanh(acc[mt][nt2][2] + bv0);
                    res[mt][nt2][3] += fast_tanh(acc[mt][nt2][3] + bv1);
                    acc[mt][nt2][0] = 0.f; acc[mt][nt2][1] = 0.f;
                    acc[mt][nt2][2] = 0.f; acc[mt][nt2][3] = 0.f;
                }
        }
    }

    // accumulate onto the emb@W1 term already in out
#pragma unroll
    for (int mt = 0; mt < 2; mt++)
#pragma unroll
        for (int nt = 0; nt < 4; nt++) {
            int c = warp_n * 32 + nt * 8 + qid * 2;
            int r0 = rowBase + warp_m * 32 + mt * 16 + grp;
            if (r0 < M) {
                float2 o = *(float2*)(out + (size_t)r0 * 128 + c);
                o.x += res[mt][nt][0];
                o.y += res[mt][nt][1];
                *(float2*)(out + (size_t)r0 * 128 + c) = o;
            }
            int r1 = r0 + 8;
            if (r1 < M) {
                float2 o = *(float2*)(out + (size_t)r1 * 128 + c);
                o.x += res[mt][nt][2];
                o.y += res[mt][nt][3];
                *(float2*)(out + (size_t)r1 * 128 + c) = o;
            }
        }
}

// ------------------------- launch ------------------------------------------
extern "C" void kernel_launch(void* const* d_in, const int* in_sizes, int n_in,
                              void* d_out, int out_size) {
    const float* emb = (const float*)d_in[0];
    const float* Wae = (const float*)d_in[1];
    const float* bae = (const float*)d_in[2];
    const float* w0w = (const float*)d_in[3];
    const float* w0b = (const float*)d_in[4];
    const float* War = (const float*)d_in[5];
    const float* bar = (const float*)d_in[6];
    const float* w1w = (const float*)d_in[7];
    const float* w1b = (const float*)d_in[8];
    const float* W1  = (const float*)d_in[9];
    const float* b1  = (const float*)d_in[10];
    const float* W2  = (const float*)d_in[11];
    const float* b2  = (const float*)d_in[12];
    const float* W3  = (const float*)d_in[13];
    const float* b3  = (const float*)d_in[14];
    const int* er_src = (const int*)d_in[15];
    const int* er_dst = (const int*)d_in[16];
    const int* ee_src = (const int*)d_in[17];
    const int* ee_dst = (const int*)d_in[18];
    const int* rr_src = (const int*)d_in[19];
    const int* rr_dst = (const int*)d_in[20];

    int N   = in_sizes[0] / 128;
    int Eer = in_sizes[15];
    int Eee = in_sizes[17];
    int Err = in_sizes[19];
    float* out = (float*)d_out;

    // streams/events created once, on the (uncaptured) correctness call;
    // reused by the capture call so capture itself allocates nothing.
    static cudaStream_t st1 = nullptr, st2 = nullptr;
    static cudaEvent_t ev0 = nullptr, ev1 = nullptr, ev2 = nullptr;
    if (st1 == nullptr) {
        cudaStreamCreateWithFlags(&st1, cudaStreamNonBlocking);
        cudaStreamCreateWithFlags(&st2, cudaStreamNonBlocking);
        cudaEventCreateWithFlags(&ev0, cudaEventDisableTiming);
        cudaEventCreateWithFlags(&ev1, cudaEventDisableTiming);
        cudaEventCreateWithFlags(&ev2, cudaEventDisableTiming);
    }

    cudaFuncSetAttribute(gemm_pre_mma, cudaFuncAttributeMaxDynamicSharedMemorySize, SMEM_PRE);
    cudaFuncSetAttribute(gemm_w1_mma,  cudaFuncAttributeMaxDynamicSharedMemorySize, SMEM_PRE);
    cudaFuncSetAttribute(gemm_out_mma, cudaFuncAttributeMaxDynamicSharedMemorySize, SMEM_OUT);

    setup_all<<<4544, 256>>>(emb, N, Wae, War, bae, bar, w0w, w1w, W1, W2, W3);
    cudaEventRecord(ev0, 0);

    // side stream 1: mean scatter (depends only on setup)
    cudaStreamWaitEvent(st1, ev0, 0);
    mean_scatter<<<(Eee + Err + 7) / 8, 256, 0, st1>>>(ee_src, ee_dst, Eee,
                                                       rr_src, rr_dst, Err);
    cudaEventRecord(ev1, st1);

    // side stream 2: emb@W1 term (depends only on setup)
    cudaStreamWaitEvent(st2, ev0, 0);
    gemm_w1_mma<<<(N + 127) / 128, 256, SMEM_PRE, st2>>>(b1, out, N);
    cudaEventRecord(ev2, st2);

    // main stream: attention chain
    dim3 gpre((N + 127) / 128, 4);
    gemm_pre_mma<<<gpre, 256, SMEM_PRE>>>(N);
    edge_attn<<<(Eer + 7) / 8, 256>>>(er_src, er_dst, Eer, w0b, w1b);

    // join
    cudaStreamWaitEvent(0, ev1, 0);
    cudaStreamWaitEvent(0, ev2, 0);
    gemm_out_mma<<<(N + 63) / 64, 256, SMEM_OUT>>>(b2, b3, out, N);
}

// round 13
// speedup vs baseline: 1.0390x; 1.0390x over previous
#include <cuda_runtime.h>
#include <cuda_bf16.h>
#include <cuda_fp16.h>
#include <cstdint>

#define MAXN 100000
#define MAXE 500000

// ------------------------- scratch (device globals, no mallocs) -------------
__device__ __align__(16) __half g_Ps16[(size_t)MAXN * 256]; // src proj fp16
__device__ __align__(16) __half g_Pt16[(size_t)MAXN * 256]; // dst proj fp16 (+bias)
__device__ __align__(16) __half g_emb16[(size_t)MAXN * 128];
// bf16 hi/lo pre-split emb (padded 128 rows for in-bounds tile reads)
__device__ __align__(16) __nv_bfloat16 g_embH[(size_t)(MAXN + 128) * 128];
__device__ __align__(16) __nv_bfloat16 g_embL[(size_t)(MAXN + 128) * 128];
// aggregates padded 128 rows: tail-tile cp.async reads stay in-bounds (padding
// is zero-initialized and never written -> harmless zeros)
__device__ __align__(16) float g_attn0[(size_t)(MAXN + 128) * 128];
__device__ __align__(16) float g_attn1[(size_t)(MAXN + 128) * 128];
__device__ __align__(16) float g_mean[(size_t)(MAXN + 128) * 128];
__device__ float g_cnt[MAXN];
__device__ float g_sum0[MAXN], g_sum1[MAXN];
__device__ float g_bias[256];                // [bae | bar]
__device__ float g_wv[256];                  // [w0w | w1w]
// bf16 weight tiles, layout [tile][khalf][n][64] (B^T, hi/lo split)
__device__ __align__(16) __nv_bfloat16 g_BpreH[4 * 16384];
__device__ __align__(16) __nv_bfloat16 g_BpreL[4 * 16384];
__device__ __align__(16) __nv_bfloat16 g_BoutH[3 * 16384];
__device__ __align__(16) __nv_bfloat16 g_BoutL[3 * 16384];

// ------------------------- PTX helpers --------------------------------------
__device__ __forceinline__ uint32_t smem_u32(const void* p) {
    uint32_t a;
    asm("{ .reg .u64 t; cvta.to.shared.u64 t, %1; cvt.u32.u64 %0, t; }" : "=r"(a) : "l"(p));
    return a;
}

#define LDM_X4(r, addr) \
    asm volatile("ldmatrix.sync.aligned.m8n8.x4.shared.b16 {%0,%1,%2,%3}, [%4];" \
        : "=r"((r)[0]), "=r"((r)[1]), "=r"((r)[2]), "=r"((r)[3]) : "r"(addr))

#define LDM_X2(r, addr) \
    asm volatile("ldmatrix.sync.aligned.m8n8.x2.shared.b16 {%0,%1}, [%2];" \
        : "=r"((r)[0]), "=r"((r)[1]) : "r"(addr))

#define MMA_BF16(c, a, b) \
    asm volatile("mma.sync.aligned.m16n8k16.row.col.f32.bf16.bf16.f32 " \
        "{%0,%1,%2,%3}, {%4,%5,%6,%7}, {%8,%9}, {%0,%1,%2,%3};" \
        : "+f"((c)[0]), "+f"((c)[1]), "+f"((c)[2]), "+f"((c)[3]) \
        : "r"((a)[0]), "r"((a)[1]), "r"((a)[2]), "r"((a)[3]), "r"((b)[0]), "r"((b)[1]))

#define CP_ASYNC16(saddr, gptr) \
    asm volatile("cp.async.cg.shared.global [%0], [%1], 16;" \
        :: "r"(saddr), "l"(gptr) : "memory")
#define CP_COMMIT() asm volatile("cp.async.commit_group;" ::: "memory")
#define CP_WAIT0()  asm volatile("cp.async.wait_group 0;" ::: "memory")

__device__ __forceinline__ void red_add4(float* p, float a, float b, float c, float d) {
    asm volatile("red.global.add.v4.f32 [%0], {%1, %2, %3, %4};"
        :: "l"(p), "f"(a), "f"(b), "f"(c), "f"(d) : "memory");
}

// ------------------------- fast math ---------------------------------------
__device__ __forceinline__ float fast_tanh(float x) {
    float e;
    asm("ex2.approx.f32 %0, %1;" : "=f"(e) : "f"(x * 2.885390082f));
    float r;
    asm("rcp.approx.f32 %0, %1;" : "=f"(r) : "f"(e + 1.0f));
    return fmaf(-2.0f, r, 1.0f);
}

__device__ __forceinline__ float fast_exp(float x) {
    float e;
    asm("ex2.approx.f32 %0, %1;" : "=f"(e) : "f"(x * 1.4426950408889634f));
    return e;
}

// ------------------------- merged setup kernel ------------------------------
__global__ void setup_all(const float* __restrict__ emb, int N,
                          const float* __restrict__ Wae, const float* __restrict__ War,
                          const float* __restrict__ bae, const float* __restrict__ bar,
                          const float* __restrict__ w0w, const float* __restrict__ w1w,
                          const float* __restrict__ W1, const float* __restrict__ W2,
                          const float* __restrict__ W3) {
    int b = blockIdx.x;
    if (b < 2048) {
        size_t stride = (size_t)2048 * 256;
        size_t i = (size_t)b * 256 + threadIdx.x;
        size_t n4 = (size_t)N * 32;
        float4 z = make_float4(0.f, 0.f, 0.f, 0.f);
        float4* a4 = (float4*)g_attn0;
        float4* b4 = (float4*)g_attn1;
        float4* m4 = (float4*)g_mean;
        for (size_t j = i; j < n4; j += stride) { a4[j] = z; b4[j] = z; m4[j] = z; }
        for (size_t j = i; j < (size_t)N; j += stride) {
            g_cnt[j] = 0.f; g_sum0[j] = 0.f; g_sum1[j] = 0.f;
        }
    } else if (b < 4096) {
        size_t stride = (size_t)2048 * 256;
        size_t i = (size_t)(b - 2048) * 256 + threadIdx.x;
        int total2 = N * 64;
        __half2* d16 = (__half2*)g_emb16;
        __nv_bfloat162* dH = (__nv_bfloat162*)g_embH;
        __nv_bfloat162* dL = (__nv_bfloat162*)g_embL;
        const float2* src = (const float2*)emb;
        for (size_t j = i; j < (size_t)total2; j += stride) {
            float2 v = src[j];
            __nv_bfloat162 h = __floats2bfloat162_rn(v.x, v.y);
            __nv_bfloat162 l = __floats2bfloat162_rn(v.x - __bfloat162float(h.x),
                                                     v.y - __bfloat162float(h.y));
            dH[j] = h;
            dL[j] = l;
            d16[j] = __floats2half2_rn(v.x, v.y);
        }
    } else {
        int i = (b - 4096) * 256 + threadIdx.x;
        if (i < 65536) {
            int y = i >> 14, r = i & 16383, k = r >> 7, n = r & 127;
            int cc = (y << 7) + n;
            float v;
            if (y == 0)      v = Wae[(128 + k) * 128 + cc];
            else if (y == 1) v = War[k * 128 + (cc - 128)];
            else if (y == 2) v = Wae[k * 128 + (cc - 256)];
            else             v = War[(128 + k) * 128 + (cc - 384)];
            __nv_bfloat16 h = __float2bfloat16(v);
            __nv_bfloat16 l = __float2bfloat16(v - __bfloat162float(h));
            int kh = k >> 6, kk = k & 63;
            size_t off = (size_t)y * 16384 + kh * 8192 + n * 64 + kk;
            g_BpreH[off] = h;
            g_BpreL[off] = l;
        } else if (i < 65536 + 49152) {
            int j = i - 65536;
            int t = j >> 14, r = j & 16383, k = r >> 7, n = r & 127;
            const float* W = (t == 0) ? W1 : (t == 1) ? W2 : W3;
            float v = W[k * 128 + n];
            __nv_bfloat16 h = __float2bfloat16(v);
            __nv_bfloat16 l = __float2bfloat16(v - __bfloat162float(h));
            int kh = k >> 6, kk = k & 63;
            size_t off = (size_t)t * 16384 + kh * 8192 + n * 64 + kk;
            g_BoutH[off] = h;
            g_BoutL[off] = l;
        }
        if (i < 128) {
            g_bias[i] = bae[i];  g_bias[128 + i] = bar[i];
            g_wv[i]   = w0w[i];  g_wv[128 + i]   = w1w[i];
        }
    }
}

// ------------------------- GEMM machinery -----------------------------------
// gemm_pre stage (73728 B): AH @0, AL @18432, BH @36864, BL @55296 (128-row A).
#define STG   73728u
#define SMEM_PRE (2 * STG)

// gemm_out stage (M=64 tile, 55296 B): AH @0 (9216), AL @9216, BH @18432, BL @36864.
#define OF32A  55296u                 // fp32 scratch A (64x64 = 16384 B)
#define OF32B  71680u                 // fp32 scratch B
#define OBIAS  88064u
#define SMEM_OUT (OBIAS + 1536u)      // 89600 B -> 2 CTA/SM

__device__ __forceinline__ uint32_t b2u(__nv_bfloat162 v) {
    return *reinterpret_cast<uint32_t*>(&v);
}

// cp.async copy of a 128x64 bf16 tile: 128 rows x 8 int4, dst stride 9 int4
__device__ __forceinline__ void cp_rows(uint32_t sbase, const int4* __restrict__ src,
                                        int srcStride4, int tid) {
#pragma unroll
    for (int i = 0; i < 4; i++) {
        int idx = tid + i * 256;
        int n = idx >> 3, q = idx & 7;
        CP_ASYNC16(sbase + (uint32_t)(n * 9 + q) * 16, src + (size_t)n * srcStride4 + q);
    }
}

// cp.async copy of a 64x64 bf16 tile: 64 rows x 8 int4
__device__ __forceinline__ void cp_rows64(uint32_t sbase, const int4* __restrict__ src,
                                          int srcStride4, int tid) {
#pragma unroll
    for (int i = 0; i < 2; i++) {
        int idx = tid + i * 256;
        int n = idx >> 3, q = idx & 7;
        CP_ASYNC16(sbase + (uint32_t)(n * 9 + q) * 16, src + (size_t)n * srcStride4 + q);
    }
}

// cp.async copy of a 64x64 fp32 half-tile into scratch (row*16+q float4s)
__device__ __forceinline__ void cp_f32_half64(uint32_t sbase, const float4* __restrict__ src,
                                              int kh, int tid) {
#pragma unroll
    for (int i = 0; i < 4; i++) {
        int idx = tid + i * 256;
        int row = idx >> 4, q = idx & 15;
        CP_ASYNC16(sbase + (uint32_t)(row * 16 + q) * 16,
                   src + (size_t)row * 32 + kh * 16 + q);
    }
}

__device__ __forceinline__ void split_store(__nv_bfloat16* sAh, __nv_bfloat16* sAl,
                                            int row, int q, float4 v) {
    __nv_bfloat162 h01 = __floats2bfloat162_rn(v.x, v.y);
    __nv_bfloat162 h23 = __floats2bfloat162_rn(v.z, v.w);
    __nv_bfloat162 l01 = __floats2bfloat162_rn(v.x - __bfloat162float(h01.x),
                                               v.y - __bfloat162float(h01.y));
    __nv_bfloat162 l23 = __floats2bfloat162_rn(v.z - __bfloat162float(h23.x),
                                               v.w - __bfloat162float(h23.y));
    *(uint2*)(sAh + row * 72 + q * 4) = make_uint2(b2u(h01), b2u(h23));
    *(uint2*)(sAl + row * 72 + q * 4) = make_uint2(b2u(l01), b2u(l23));
}

// 128-row warp-tile mma (gemm_pre): acc[4][4][4]
__device__ __forceinline__ void mma_half(float acc[4][4][4], uint32_t base,
                                         int warp_m, int warp_n, int lane) {
    int arow = warp_m * 64 + (lane & 15);
    int acolB = (lane >> 4) * 16;
    int brow = warp_n * 32 + (lane & 7);
    int bcolB = ((lane >> 3) & 1) * 16;
    uint32_t aoff = base + 0u     + arow * 144 + acolB;
    uint32_t loff = base + 18432u + arow * 144 + acolB;
    uint32_t boff = base + 36864u + brow * 144 + bcolB;
    uint32_t moff = base + 55296u + brow * 144 + bcolB;

#pragma unroll
    for (int ks = 0; ks < 4; ks++) {
        uint32_t kbB = ks * 32;
        uint32_t ah[4][4], al[4][4], bh[4][2], bl[4][2];
#pragma unroll
        for (int mt = 0; mt < 4; mt++) {
            uint32_t off = mt * 16 * 144 + kbB;
            LDM_X4(ah[mt], aoff + off);
            LDM_X4(al[mt], loff + off);
        }
#pragma unroll
        for (int nt = 0; nt < 4; nt++) {
            uint32_t off = nt * 8 * 144 + kbB;
            LDM_X2(bh[nt], boff + off);
            LDM_X2(bl[nt], moff + off);
        }
#pragma unroll
        for (int mt = 0; mt < 4; mt++)
#pragma unroll
            for (int nt = 0; nt < 4; nt++) {
                MMA_BF16(acc[mt][nt], ah[mt], bh[nt]);
                MMA_BF16(acc[mt][nt], al[mt], bh[nt]);
                MMA_BF16(acc[mt][nt], ah[mt], bl[nt]);
            }
    }
}

// 64-row warp-tile mma (gemm_out): acc[2][4][4], warp tile 32x32
__device__ __forceinline__ void mma_half64(float acc[2][4][4], uint32_t base,
                                           int warp_m, int warp_n, int lane) {
    int arow = warp_m * 32 + (lane & 15);
    int acolB = (lane >> 4) * 16;
    int brow = warp_n * 32 + (lane & 7);
    int bcolB = ((lane >> 3) & 1) * 16;
    uint32_t aoff = base + 0u     + arow * 144 + acolB;
    uint32_t loff = base + 9216u  + arow * 144 + acolB;
    uint32_t boff = base + 18432u + brow * 144 + bcolB;
    uint32_t moff = base + 36864u + brow * 144 + bcolB;

#pragma unroll
    for (int ks = 0; ks < 4; ks++) {
        uint32_t kbB = ks * 32;
        uint32_t ah[2][4], al[2][4], bh[4][2], bl[4][2];
#pragma unroll
        for (int mt = 0; mt < 2; mt++) {
            uint32_t off = mt * 16 * 144 + kbB;
            LDM_X4(ah[mt], aoff + off);
            LDM_X4(al[mt], loff + off);
        }
#pragma unroll
        for (int nt = 0; nt < 4; nt++) {
            uint32_t off = nt * 8 * 144 + kbB;
            LDM_X2(bh[nt], boff + off);
            LDM_X2(bl[nt], moff + off);
        }
#pragma unroll
        for (int mt = 0; mt < 2; mt++)
#pragma unroll
            for (int nt = 0; nt < 4; nt++) {
                MMA_BF16(acc[mt][nt], ah[mt], bh[nt]);
                MMA_BF16(acc[mt][nt], al[mt], bh[nt]);
                MMA_BF16(acc[mt][nt], ah[mt], bl[nt]);
            }
    }
}

// ------------------------- pre-projection GEMM (pipelined, 1 CTA/SM) --------
__global__ __launch_bounds__(256) void gemm_pre_mma(int M) {
    extern __shared__ char smc[];
    uint32_t sb = smem_u32(smc);
    int tid = threadIdx.x, lane = tid & 31, wid = tid >> 5;
    int rowBase = blockIdx.x * 128, yt = blockIdx.y;
    int warp_m = wid & 1, warp_n = wid >> 1;
    int grp = lane >> 2, qid = lane & 3;

    float acc[4][4][4];
#pragma unroll
    for (int mt = 0; mt < 4; mt++)
#pragma unroll
        for (int nt = 0; nt < 4; nt++)
#pragma unroll
            for (int j = 0; j < 4; j++) acc[mt][nt][j] = 0.f;

    cp_rows(sb + 0u,      (const int4*)g_embH + (size_t)rowBase * 16, 16, tid);
    cp_rows(sb + 18432u,  (const int4*)g_embL + (size_t)rowBase * 16, 16, tid);
    cp_rows(sb + 36864u,  (const int4*)(g_BpreH + (size_t)yt * 16384), 8, tid);
    cp_rows(sb + 55296u,  (const int4*)(g_BpreL + (size_t)yt * 16384), 8, tid);
    CP_COMMIT();

#pragma unroll 1
    for (int kh = 0; kh < 2; kh++) {
        CP_WAIT0();
        __syncthreads();
        if (kh == 0) {
            cp_rows(sb + STG + 0u,     (const int4*)g_embH + (size_t)rowBase * 16 + 8, 16, tid);
            cp_rows(sb + STG + 18432u, (const int4*)g_embL + (size_t)rowBase * 16 + 8, 16, tid);
            cp_rows(sb + STG + 36864u, (const int4*)(g_BpreH + (size_t)yt * 16384 + 8192), 8, tid);
            cp_rows(sb + STG + 55296u, (const int4*)(g_BpreL + (size_t)yt * 16384 + 8192), 8, tid);
            CP_COMMIT();
        }
        mma_half(acc, sb + (uint32_t)kh * STG, warp_m, warp_n, lane);
    }

    __half* Cbase;
    int colOff;
    if (yt < 2) { Cbase = g_Ps16; colOff = yt * 128; }
    else        { Cbase = g_Pt16; colOff = (yt - 2) * 128; }
    bool addBias = (yt >= 2);
#pragma unroll
    for (int mt = 0; mt < 4; mt++) {
#pragma unroll
        for (int nt = 0; nt < 4; nt++) {
            int c = colOff + warp_n * 32 + nt * 8 + qid * 2;
            float b0 = 0.f, b1 = 0.f;
            if (addBias) { b0 = g_bias[c]; b1 = g_bias[c + 1]; }
            int r0 = rowBase + warp_m * 64 + mt * 16 + grp;
            if (r0 < M)
                *(__half2*)(Cbase + (size_t)r0 * 256 + c) =
                    __floats2half2_rn(acc[mt][nt][0] + b0, acc[mt][nt][1] + b1);
            int r1 = r0 + 8;
            if (r1 < M)
                *(__half2*)(Cbase + (size_t)r1 * 256 + c) =
                    __floats2half2_rn(acc[mt][nt][2] + b0, acc[mt][nt][3] + b1);
        }
    }
}

// ------------------------- attention edge pass -------------------------------
__global__ void edge_attn(const int* __restrict__ er_src, const int* __restrict__ er_dst,
                          int Eer,
                          const float* __restrict__ w0b, const float* __restrict__ w1b) {
    int wid = threadIdx.x >> 5, lane = threadIdx.x & 31;
    int gw = blockIdx.x * 8 + wid;
    if (gw >= Eer) return;
    int s = er_src[gw], t = er_dst[gw];
    uint4 a = ((const uint4*)(g_Ps16 + (size_t)s * 256))[lane];
    uint4 b = ((const uint4*)(g_Pt16 + (size_t)t * 256))[lane];
    float4 w0 = ((const float4*)g_wv)[lane * 2];
    float4 w1 = ((const float4*)g_wv)[lane * 2 + 1];

    const __half2* ah = reinterpret_cast<const __half2*>(&a);
    const __half2* bh = reinterpret_cast<const __half2*>(&b);
    float part = 0.f;
    float wv[8] = {w0.x, w0.y, w0.z, w0.w, w1.x, w1.y, w1.z, w1.w};
#pragma unroll
    for (int j = 0; j < 4; j++) {
        float2 xa = __half22float2(ah[j]);
        float2 xb = __half22float2(bh[j]);
        part += fast_tanh(xa.x + xb.x) * wv[2 * j]
              + fast_tanh(xa.y + xb.y) * wv[2 * j + 1];
    }
#pragma unroll
    for (int o = 1; o <= 8; o <<= 1)
        part += __shfl_xor_sync(0xFFFFFFFFu, part, o);
    float other = __shfl_xor_sync(0xFFFFFFFFu, part, 16);

    float p0, p1;
    if (lane == 0) {
        p0 = fast_exp(part + w0b[0]);
        p1 = fast_exp(other + w1b[0]);
        atomicAdd(g_sum0 + s, p0);
        atomicAdd(g_sum1 + t, p1);
    }
    p0 = __shfl_sync(0xFFFFFFFFu, p0, 0);
    p1 = __shfl_sync(0xFFFFFFFFu, p1, 0);

    uint2 rv = ((const uint2*)(g_emb16 + (size_t)t * 128))[lane];
    const __half2* rh = reinterpret_cast<const __half2*>(&rv);
    float2 r01 = __half22float2(rh[0]);
    float2 r23 = __half22float2(rh[1]);
    red_add4(g_attn0 + (size_t)s * 128 + lane * 4,
             p0 * r01.x, p0 * r01.y, p0 * r23.x, p0 * r23.y);

    uint2 hv = ((const uint2*)(g_emb16 + (size_t)s * 128))[lane];
    const __half2* hh = reinterpret_cast<const __half2*>(&hv);
    float2 h01 = __half22float2(hh[0]);
    float2 h23 = __half22float2(hh[1]);
    red_add4(g_attn1 + (size_t)t * 128 + lane * 4,
             p1 * h01.x, p1 * h01.y, p1 * h23.x, p1 * h23.y);
}

// ------------------------- mean edge pass (side stream) ---------------------
__global__ void mean_scatter(const int* __restrict__ ee_src, const int* __restrict__ ee_dst,
                             int Eee,
                             const int* __restrict__ rr_src, const int* __restrict__ rr_dst,
                             int Err) {
    int wid = threadIdx.x >> 5, lane = threadIdx.x & 31;
    int gw = blockIdx.x * 8 + wid;
    int total = Eee + Err;
    if (gw >= total) return;
    int s, t;
    if (gw < Eee) { s = ee_src[gw]; t = ee_dst[gw]; }
    else          { s = rr_src[gw - Eee]; t = rr_dst[gw - Eee]; }

    uint2 hv = ((const uint2*)(g_emb16 + (size_t)t * 128))[lane];
    const __half2* hh = reinterpret_cast<const __half2*>(&hv);
    float2 v01 = __half22float2(hh[0]);
    float2 v23 = __half22float2(hh[1]);
    red_add4(g_mean + (size_t)s * 128 + lane * 4, v01.x, v01.y, v23.x, v23.y);
    if (lane == 0) atomicAdd(g_cnt + s, 1.0f);
}

// ------------------------- fused output GEMM (M=64 tile, 2 CTA/SM) ----------
// 6 stages s=(t,kh), single bf16 stage buffer + fp32 smem scratch.
__global__ __launch_bounds__(256, 2) void gemm_out_mma(const float* __restrict__ b1,
                                                       const float* __restrict__ b2,
                                                       const float* __restrict__ b3,
                                                       float* __restrict__ out, int M) {
    extern __shared__ char smc[];
    float* sbias = (float*)(smc + OBIAS);
    uint32_t sb = smem_u32(smc);
    int tid = threadIdx.x, lane = tid & 31, wid = tid >> 5;
    int rowBase = blockIdx.x * 64;
    int warp_m = wid & 1, warp_n = wid >> 1;
    int grp = lane >> 2, qid = lane & 3;

    if (tid < 128) {
        sbias[tid]       = b1[tid];
        sbias[128 + tid] = b2[tid];
        sbias[256 + tid] = b3[tid];
    }

    float res[2][4][4], acc[2][4][4];
#pragma unroll
    for (int mt = 0; mt < 2; mt++)
#pragma unroll
        for (int nt = 0; nt < 4; nt++)
#pragma unroll
            for (int j = 0; j < 4; j++) { res[mt][nt][j] = 0.f; acc[mt][nt][j] = 0.f; }

    // prologue: stage 0 = (t=0, kh=0)
    cp_rows64(sb + 0u,     (const int4*)g_embH + (size_t)rowBase * 16, 16, tid);
    cp_rows64(sb + 9216u,  (const int4*)g_embL + (size_t)rowBase * 16, 16, tid);
    cp_rows(sb + 18432u, (const int4*)g_BoutH, 8, tid);
    cp_rows(sb + 36864u, (const int4*)g_BoutL, 8, tid);
    CP_COMMIT();

    float ps0[4], ps1[4];
    int rbq = tid >> 4;   // thread's convert-slot base row (0..15)

#pragma unroll 1
    for (int s = 0; s < 6; s++) {
        int t = s >> 1, kh = s & 1;
        int ns = s + 1;
        int nt = ns >> 1, nkh = ns & 1;
        CP_WAIT0();
        __syncthreads();

        // convert current stage's A from fp32 scratch (t>=1)
        if (t >= 1) {
            __nv_bfloat16* cAh = (__nv_bfloat16*)smc;
            __nv_bfloat16* cAl = (__nv_bfloat16*)(smc + 9216);
#pragma unroll
            for (int i = 0; i < 4; i++) {
                int row = rbq + i * 16;
                int q = tid & 15;
                float4 v;
                if (t == 1) {
                    float4 v0 = *(const float4*)(smc + OF32A + (size_t)(row * 16 + q) * 16);
                    float4 v1 = *(const float4*)(smc + OF32B + (size_t)(row * 16 + q) * 16);
                    float i0 = __fdividef(1.0f, ps0[i] + 1e-9f);
                    float i1 = __fdividef(1.0f, ps1[i] + 1e-9f);
                    v.x = v0.x * i0 + v1.x * i1;
                    v.y = v0.y * i0 + v1.y * i1;
                    v.z = v0.z * i0 + v1.z * i1;
                    v.w = v0.w * i0 + v1.w * i1;
                } else {
                    float4 v0 = *(const float4*)(smc + OF32A + (size_t)(row * 16 + q) * 16);
                    float rc = 1.0f / fmaxf(ps0[i], 1.0f);
                    v.x = v0.x * rc; v.y = v0.y * rc;
                    v.z = v0.z * rc; v.w = v0.w * rc;
                }
                split_store(cAh, cAl, row, q, v);
            }
            __syncthreads();
        }

        // scratch prefetch for stage s+1 (scratch is free now) — overlaps mma
        if (ns < 6 && nt >= 1) {
            if (nt == 1) {
                cp_f32_half64(sb + OF32A, (const float4*)g_attn0 + (size_t)rowBase * 32, nkh, tid);
                cp_f32_half64(sb + OF32B, (const float4*)g_attn1 + (size_t)rowBase * 32, nkh, tid);
#pragma unroll
                for (int i = 0; i < 4; i++) {
                    int gr = rowBase + rbq + i * 16;
                    bool ok = gr < M;
                    ps0[i] = ok ? g_sum0[gr] : 1.f;
                    ps1[i] = ok ? g_sum1[gr] : 1.f;
                }
            } else {
                cp_f32_half64(sb + OF32A, (const float4*)g_mean + (size_t)rowBase * 32, nkh, tid);
#pragma unroll
                for (int i = 0; i < 4; i++) {
                    int gr = rowBase + rbq + i * 16;
                    ps0[i] = (gr < M) ? g_cnt[gr] : 1.f;
                }
            }
            CP_COMMIT();
        }

        mma_half64(acc, sb, warp_m, warp_n, lane);
        __syncthreads();   // stage buffer free

        // B (+ emb A) prefetch for stage s+1 into the single stage buffer
        if (ns < 6) {
            cp_rows(sb + 18432u, (const int4*)(g_BoutH + (size_t)nt * 16384 + nkh * 8192), 8, tid);
            cp_rows(sb + 36864u, (const int4*)(g_BoutL + (size_t)nt * 16384 + nkh * 8192), 8, tid);
            if (nt == 0) {
                cp_rows64(sb + 0u,    (const int4*)g_embH + (size_t)rowBase * 16 + nkh * 8, 16, tid);
                cp_rows64(sb + 9216u, (const int4*)g_embL + (size_t)rowBase * 16 + nkh * 8, 16, tid);
            }
            CP_COMMIT();
        }

        if (kh == 1) {  // term epilogue (ALU, overlaps the loads just issued)
            const float* bias = sbias + t * 128;
#pragma unroll
            for (int mt = 0; mt < 2; mt++)
#pragma unroll
                for (int nt2 = 0; nt2 < 4; nt2++) {
                    int c = warp_n * 32 + nt2 * 8 + qid * 2;
                    float bv0 = bias[c], bv1 = bias[c + 1];
                    res[mt][nt2][0] += fast_tanh(acc[mt][nt2][0] + bv0);
                    res[mt][nt2][1] += fast_tanh(acc[mt][nt2][1] + bv1);
                    res[mt][nt2][2] += fast_tanh(acc[mt][nt2][2] + bv0);
                    res[mt][nt2][3] += fast_tanh(acc[mt][nt2][3] + bv1);
                    acc[mt][nt2][0] = 0.f; acc[mt][nt2][1] = 0.f;
                    acc[mt][nt2][2] = 0.f; acc[mt][nt2][3] = 0.f;
                }
        }
    }

#pragma unroll
    for (int mt = 0; mt < 2; mt++)
#pragma unroll
        for (int nt = 0; nt < 4; nt++) {
            int c = warp_n * 32 + nt * 8 + qid * 2;
            int r0 = rowBase + warp_m * 32 + mt * 16 + grp;
            if (r0 < M)
                *(float2*)(out + (size_t)r0 * 128 + c) =
                    make_float2(res[mt][nt][0], res[mt][nt][1]);
            int r1 = r0 + 8;
            if (r1 < M)
                *(float2*)(out + (size_t)r1 * 128 + c) =
                    make_float2(res[mt][nt][2], res[mt][nt][3]);
        }
}

// ------------------------- launch ------------------------------------------
extern "C" void kernel_launch(void* const* d_in, const int* in_sizes, int n_in,
                              void* d_out, int out_size) {
    const float* emb = (const float*)d_in[0];
    const float* Wae = (const float*)d_in[1];
    const float* bae = (const float*)d_in[2];
    const float* w0w = (const float*)d_in[3];
    const float* w0b = (const float*)d_in[4];
    const float* War = (const float*)d_in[5];
    const float* bar = (const float*)d_in[6];
    const float* w1w = (const float*)d_in[7];
    const float* w1b = (const float*)d_in[8];
    const float* W1  = (const float*)d_in[9];
    const float* b1  = (const float*)d_in[10];
    const float* W2  = (const float*)d_in[11];
    const float* b2  = (const float*)d_in[12];
    const float* W3  = (const float*)d_in[13];
    const float* b3  = (const float*)d_in[14];
    const int* er_src = (const int*)d_in[15];
    const int* er_dst = (const int*)d_in[16];
    const int* ee_src = (const int*)d_in[17];
    const int* ee_dst = (const int*)d_in[18];
    const int* rr_src = (const int*)d_in[19];
    const int* rr_dst = (const int*)d_in[20];

    int N   = in_sizes[0] / 128;
    int Eer = in_sizes[15];
    int Eee = in_sizes[17];
    int Err = in_sizes[19];
    float* out = (float*)d_out;

    // streams/events created once, on the (uncaptured) correctness call;
    // reused by the capture call so capture itself allocates nothing.
    static cudaStream_t st1 = nullptr;
    static cudaEvent_t ev0 = nullptr, ev1 = nullptr;
    if (st1 == nullptr) {
        cudaStreamCreateWithFlags(&st1, cudaStreamNonBlocking);
        cudaEventCreateWithFlags(&ev0, cudaEventDisableTiming);
        cudaEventCreateWithFlags(&ev1, cudaEventDisableTiming);
    }

    cudaFuncSetAttribute(gemm_pre_mma, cudaFuncAttributeMaxDynamicSharedMemorySize, SMEM_PRE);
    cudaFuncSetAttribute(gemm_out_mma, cudaFuncAttributeMaxDynamicSharedMemorySize, SMEM_OUT);

    setup_all<<<4544, 256>>>(emb, N, Wae, War, bae, bar, w0w, w1w, W1, W2, W3);
    cudaEventRecord(ev0, 0);

    // side stream: mean scatter (DRAM/atomic-bound; overlaps tensor-bound
    // gemm_pre and the attention edge pass)
    cudaStreamWaitEvent(st1, ev0, 0);
    mean_scatter<<<(Eee + Err + 7) / 8, 256, 0, st1>>>(ee_src, ee_dst, Eee,
                                                       rr_src, rr_dst, Err);
    cudaEventRecord(ev1, st1);

    // main stream: attention chain
    dim3 gpre((N + 127) / 128, 4);
    gemm_pre_mma<<<gpre, 256, SMEM_PRE>>>(N);
    edge_attn<<<(Eer + 7) / 8, 256>>>(er_src, er_dst, Eer, w0b, w1b);

    // join, then fused output GEMM (emb + attn + mean terms)
    cudaStreamWaitEvent(0, ev1, 0);
    gemm_out_mma<<<(N + 63) / 64, 256, SMEM_OUT>>>(b1, b2, b3, out, N);
}

// round 15
// speedup vs baseline: 1.0463x; 1.0070x over previous
#include <cuda_runtime.h>
#include <cuda_bf16.h>
#include <cuda_fp16.h>
#include <cstdint>

#define MAXN 100000
#define MAXE 500000

// ------------------------- scratch (device globals, no mallocs) -------------
__device__ __align__(16) __half g_Ps16[(size_t)MAXN * 256]; // src proj fp16
__device__ __align__(16) __half g_Pt16[(size_t)MAXN * 256]; // dst proj fp16 (+bias)
__device__ __align__(16) __half g_emb16[(size_t)MAXN * 128];
// bf16 hi/lo pre-split emb (padded 128 rows for in-bounds tile reads)
__device__ __align__(16) __nv_bfloat16 g_embH[(size_t)(MAXN + 128) * 128];
__device__ __align__(16) __nv_bfloat16 g_embL[(size_t)(MAXN + 128) * 128];
// aggregates padded 128 rows: tail-tile cp.async reads stay in-bounds (padding
// is zero-initialized and never written -> harmless zeros)
__device__ __align__(16) float g_attn0[(size_t)(MAXN + 128) * 128];
__device__ __align__(16) float g_attn1[(size_t)(MAXN + 128) * 128];
__device__ __align__(16) float g_mean[(size_t)(MAXN + 128) * 128];
__device__ float g_cnt[MAXN];
__device__ float g_sum0[MAXN], g_sum1[MAXN];
__device__ float g_bias[256];                // [bae | bar]
__device__ float g_wv[256];                  // [w0w | w1w]
// bf16 weight tiles, layout [tile][khalf][n][64] (B^T, hi/lo split)
__device__ __align__(16) __nv_bfloat16 g_BpreH[4 * 16384];
__device__ __align__(16) __nv_bfloat16 g_BpreL[4 * 16384];
__device__ __align__(16) __nv_bfloat16 g_BoutH[3 * 16384];
__device__ __align__(16) __nv_bfloat16 g_BoutL[3 * 16384];

// ------------------------- PTX helpers --------------------------------------
__device__ __forceinline__ uint32_t smem_u32(const void* p) {
    uint32_t a;
    asm("{ .reg .u64 t; cvta.to.shared.u64 t, %1; cvt.u32.u64 %0, t; }" : "=r"(a) : "l"(p));
    return a;
}

#define LDM_X4(r, addr) \
    asm volatile("ldmatrix.sync.aligned.m8n8.x4.shared.b16 {%0,%1,%2,%3}, [%4];" \
        : "=r"((r)[0]), "=r"((r)[1]), "=r"((r)[2]), "=r"((r)[3]) : "r"(addr))

#define LDM_X2(r, addr) \
    asm volatile("ldmatrix.sync.aligned.m8n8.x2.shared.b16 {%0,%1}, [%2];" \
        : "=r"((r)[0]), "=r"((r)[1]) : "r"(addr))

#define MMA_BF16(c, a, b) \
    asm volatile("mma.sync.aligned.m16n8k16.row.col.f32.bf16.bf16.f32 " \
        "{%0,%1,%2,%3}, {%4,%5,%6,%7}, {%8,%9}, {%0,%1,%2,%3};" \
        : "+f"((c)[0]), "+f"((c)[1]), "+f"((c)[2]), "+f"((c)[3]) \
        : "r"((a)[0]), "r"((a)[1]), "r"((a)[2]), "r"((a)[3]), "r"((b)[0]), "r"((b)[1]))

#define CP_ASYNC16(saddr, gptr) \
    asm volatile("cp.async.cg.shared.global [%0], [%1], 16;" \
        :: "r"(saddr), "l"(gptr) : "memory")
#define CP_COMMIT() asm volatile("cp.async.commit_group;" ::: "memory")
#define CP_WAIT0()  asm volatile("cp.async.wait_group 0;" ::: "memory")

__device__ __forceinline__ void red_add4(float* p, float a, float b, float c, float d) {
    asm volatile("red.global.add.v4.f32 [%0], {%1, %2, %3, %4};"
        :: "l"(p), "f"(a), "f"(b), "f"(c), "f"(d) : "memory");
}

// ------------------------- fast math ---------------------------------------
__device__ __forceinline__ float fast_tanh(float x) {
    float e;
    asm("ex2.approx.f32 %0, %1;" : "=f"(e) : "f"(x * 2.885390082f));
    float r;
    asm("rcp.approx.f32 %0, %1;" : "=f"(r) : "f"(e + 1.0f));
    return fmaf(-2.0f, r, 1.0f);
}

__device__ __forceinline__ float fast_exp(float x) {
    float e;
    asm("ex2.approx.f32 %0, %1;" : "=f"(e) : "f"(x * 1.4426950408889634f));
    return e;
}

// ------------------------- setup: zero aggregates (side stream) -------------
__global__ void setup_zero(int N) {
    size_t stride = (size_t)gridDim.x * blockDim.x;
    size_t i = (size_t)blockIdx.x * blockDim.x + threadIdx.x;
    size_t n4 = (size_t)N * 32;
    float4 z = make_float4(0.f, 0.f, 0.f, 0.f);
    float4* a4 = (float4*)g_attn0;
    float4* b4 = (float4*)g_attn1;
    float4* m4 = (float4*)g_mean;
    for (size_t j = i; j < n4; j += stride) { a4[j] = z; b4[j] = z; m4[j] = z; }
    for (size_t j = i; j < (size_t)N; j += stride) {
        g_cnt[j] = 0.f; g_sum0[j] = 0.f; g_sum1[j] = 0.f;
    }
}

// ------------------------- setup: emb split + weight prep (main stream) -----
__global__ void setup_main(const float* __restrict__ emb, int N,
                           const float* __restrict__ Wae, const float* __restrict__ War,
                           const float* __restrict__ bae, const float* __restrict__ bar,
                           const float* __restrict__ w0w, const float* __restrict__ w1w,
                           const float* __restrict__ W1, const float* __restrict__ W2,
                           const float* __restrict__ W3) {
    int b = blockIdx.x;
    if (b < 2048) {
        size_t stride = (size_t)2048 * 256;
        size_t i = (size_t)b * 256 + threadIdx.x;
        int total2 = N * 64;
        __half2* d16 = (__half2*)g_emb16;
        __nv_bfloat162* dH = (__nv_bfloat162*)g_embH;
        __nv_bfloat162* dL = (__nv_bfloat162*)g_embL;
        const float2* src = (const float2*)emb;
        for (size_t j = i; j < (size_t)total2; j += stride) {
            float2 v = src[j];
            __nv_bfloat162 h = __floats2bfloat162_rn(v.x, v.y);
            __nv_bfloat162 l = __floats2bfloat162_rn(v.x - __bfloat162float(h.x),
                                                     v.y - __bfloat162float(h.y));
            dH[j] = h;
            dL[j] = l;
            d16[j] = __floats2half2_rn(v.x, v.y);
        }
    } else {
        int i = (b - 2048) * 256 + threadIdx.x;
        if (i < 65536) {
            int y = i >> 14, r = i & 16383, k = r >> 7, n = r & 127;
            int cc = (y << 7) + n;
            float v;
            if (y == 0)      v = Wae[(128 + k) * 128 + cc];
            else if (y == 1) v = War[k * 128 + (cc - 128)];
            else if (y == 2) v = Wae[k * 128 + (cc - 256)];
            else             v = War[(128 + k) * 128 + (cc - 384)];
            __nv_bfloat16 h = __float2bfloat16(v);
            __nv_bfloat16 l = __float2bfloat16(v - __bfloat162float(h));
            int kh = k >> 6, kk = k & 63;
            size_t off = (size_t)y * 16384 + kh * 8192 + n * 64 + kk;
            g_BpreH[off] = h;
            g_BpreL[off] = l;
        } else if (i < 65536 + 49152) {
            int j = i - 65536;
            int t = j >> 14, r = j & 16383, k = r >> 7, n = r & 127;
            const float* W = (t == 0) ? W1 : (t == 1) ? W2 : W3;
            float v = W[k * 128 + n];
            __nv_bfloat16 h = __float2bfloat16(v);
            __nv_bfloat16 l = __float2bfloat16(v - __bfloat162float(h));
            int kh = k >> 6, kk = k & 63;
            size_t off = (size_t)t * 16384 + kh * 8192 + n * 64 + kk;
            g_BoutH[off] = h;
            g_BoutL[off] = l;
        }
        if (i < 128) {
            g_bias[i] = bae[i];  g_bias[128 + i] = bar[i];
            g_wv[i]   = w0w[i];  g_wv[128 + i]   = w1w[i];
        }
    }
}

// ------------------------- GEMM machinery -----------------------------------
// gemm_pre stage (73728 B): AH @0, AL @18432, BH @36864, BL @55296 (128-row A).
#define STG   73728u
#define SMEM_PRE (2 * STG)

// gemm_out stage (M=64 tile, 55296 B): AH @0 (9216), AL @9216, BH @18432, BL @36864.
#define OF32A  55296u                 // fp32 scratch A (64x64 = 16384 B)
#define OF32B  71680u                 // fp32 scratch B
#define OBIAS  88064u
#define SMEM_OUT (OBIAS + 1536u)      // 89600 B -> 2 CTA/SM

__device__ __forceinline__ uint32_t b2u(__nv_bfloat162 v) {
    return *reinterpret_cast<uint32_t*>(&v);
}

// cp.async copy of a 128x64 bf16 tile: 128 rows x 8 int4, dst stride 9 int4
__device__ __forceinline__ void cp_rows(uint32_t sbase, const int4* __restrict__ src,
                                        int srcStride4, int tid) {
#pragma unroll
    for (int i = 0; i < 4; i++) {
        int idx = tid + i * 256;
        int n = idx >> 3, q = idx & 7;
        CP_ASYNC16(sbase + (uint32_t)(n * 9 + q) * 16, src + (size_t)n * srcStride4 + q);
    }
}

// cp.async copy of a 64x64 bf16 tile: 64 rows x 8 int4
__device__ __forceinline__ void cp_rows64(uint32_t sbase, const int4* __restrict__ src,
                                          int srcStride4, int tid) {
#pragma unroll
    for (int i = 0; i < 2; i++) {
        int idx = tid + i * 256;
        int n = idx >> 3, q = idx & 7;
        CP_ASYNC16(sbase + (uint32_t)(n * 9 + q) * 16, src + (size_t)n * srcStride4 + q);
    }
}

// cp.async copy of a 64x64 fp32 half-tile into scratch (row*16+q float4s)
__device__ __forceinline__ void cp_f32_half64(uint32_t sbase, const float4* __restrict__ src,
                                              int kh, int tid) {
#pragma unroll
    for (int i = 0; i < 4; i++) {
        int idx = tid + i * 256;
        int row = idx >> 4, q = idx & 15;
        CP_ASYNC16(sbase + (uint32_t)(row * 16 + q) * 16,
                   src + (size_t)row * 32 + kh * 16 + q);
    }
}

__device__ __forceinline__ void split_store(__nv_bfloat16* sAh, __nv_bfloat16* sAl,
                                            int row, int q, float4 v) {
    __nv_bfloat162 h01 = __floats2bfloat162_rn(v.x, v.y);
    __nv_bfloat162 h23 = __floats2bfloat162_rn(v.z, v.w);
    __nv_bfloat162 l01 = __floats2bfloat162_rn(v.x - __bfloat162float(h01.x),
                                               v.y - __bfloat162float(h01.y));
    __nv_bfloat162 l23 = __floats2bfloat162_rn(v.z - __bfloat162float(h23.x),
                                               v.w - __bfloat162float(h23.y));
    *(uint2*)(sAh + row * 72 + q * 4) = make_uint2(b2u(h01), b2u(h23));
    *(uint2*)(sAl + row * 72 + q * 4) = make_uint2(b2u(l01), b2u(l23));
}

// 128-row warp-tile mma (gemm_pre): acc[4][4][4]
__device__ __forceinline__ void mma_half(float acc[4][4][4], uint32_t base,
                                         int warp_m, int warp_n, int lane) {
    int arow = warp_m * 64 + (lane & 15);
    int acolB = (lane >> 4) * 16;
    int brow = warp_n * 32 + (lane & 7);
    int bcolB = ((lane >> 3) & 1) * 16;
    uint32_t aoff = base + 0u     + arow * 144 + acolB;
    uint32_t loff = base + 18432u + arow * 144 + acolB;
    uint32_t boff = base + 36864u + brow * 144 + bcolB;
    uint32_t moff = base + 55296u + brow * 144 + bcolB;

#pragma unroll
    for (int ks = 0; ks < 4; ks++) {
        uint32_t kbB = ks * 32;
        uint32_t ah[4][4], al[4][4], bh[4][2], bl[4][2];
#pragma unroll
        for (int mt = 0; mt < 4; mt++) {
            uint32_t off = mt * 16 * 144 + kbB;
            LDM_X4(ah[mt], aoff + off);
            LDM_X4(al[mt], loff + off);
        }
#pragma unroll
        for (int nt = 0; nt < 4; nt++) {
            uint32_t off = nt * 8 * 144 + kbB;
            LDM_X2(bh[nt], boff + off);
            LDM_X2(bl[nt], moff + off);
        }
#pragma unroll
        for (int mt = 0; mt < 4; mt++)
#pragma unroll
            for (int nt = 0; nt < 4; nt++) {
                MMA_BF16(acc[mt][nt], ah[mt], bh[nt]);
                MMA_BF16(acc[mt][nt], al[mt], bh[nt]);
                MMA_BF16(acc[mt][nt], ah[mt], bl[nt]);
            }
    }
}

// 64-row warp-tile mma (gemm_out): acc[2][4][4], warp tile 32x32
__device__ __forceinline__ void mma_half64(float acc[2][4][4], uint32_t base,
                                           int warp_m, int warp_n, int lane) {
    int arow = warp_m * 32 + (lane & 15);
    int acolB = (lane >> 4) * 16;
    int brow = warp_n * 32 + (lane & 7);
    int bcolB = ((lane >> 3) & 1) * 16;
    uint32_t aoff = base + 0u     + arow * 144 + acolB;
    uint32_t loff = base + 9216u  + arow * 144 + acolB;
    uint32_t boff = base + 18432u + brow * 144 + bcolB;
    uint32_t moff = base + 36864u + brow * 144 + bcolB;

#pragma unroll
    for (int ks = 0; ks < 4; ks++) {
        uint32_t kbB = ks * 32;
        uint32_t ah[2][4], al[2][4], bh[4][2], bl[4][2];
#pragma unroll
        for (int mt = 0; mt < 2; mt++) {
            uint32_t off = mt * 16 * 144 + kbB;
            LDM_X4(ah[mt], aoff + off);
            LDM_X4(al[mt], loff + off);
        }
#pragma unroll
        for (int nt = 0; nt < 4; nt++) {
            uint32_t off = nt * 8 * 144 + kbB;
            LDM_X2(bh[nt], boff + off);
            LDM_X2(bl[nt], moff + off);
        }
#pragma unroll
        for (int mt = 0; mt < 2; mt++)
#pragma unroll
            for (int nt = 0; nt < 4; nt++) {
                MMA_BF16(acc[mt][nt], ah[mt], bh[nt]);
                MMA_BF16(acc[mt][nt], al[mt], bh[nt]);
                MMA_BF16(acc[mt][nt], ah[mt], bl[nt]);
            }
    }
}

// ------------------------- pre-projection GEMM ------------------------------
// 2 output tiles per CTA with A resident: stages (yt,kh) = 4, double-buffered;
// A half-tiles loaded once (buf0=k0, buf1=k1), stages 2-3 reload B slots only.
__global__ __launch_bounds__(256) void gemm_pre_mma(int M) {
    extern __shared__ char smc[];
    uint32_t sb = smem_u32(smc);
    int tid = threadIdx.x, lane = tid & 31, wid = tid >> 5;
    int rowBase = blockIdx.x * 128, ytBase = blockIdx.y * 2;
    int warp_m = wid & 1, warp_n = wid >> 1;
    int grp = lane >> 2, qid = lane & 3;

    float acc[4][4][4];
#pragma unroll
    for (int mt = 0; mt < 4; mt++)
#pragma unroll
        for (int nt = 0; nt < 4; nt++)
#pragma unroll
            for (int j = 0; j < 4; j++) acc[mt][nt][j] = 0.f;

    // prologue: buf0 = A(k0) + B(yt0,k0)
    cp_rows(sb + 0u,      (const int4*)g_embH + (size_t)rowBase * 16, 16, tid);
    cp_rows(sb + 18432u,  (const int4*)g_embL + (size_t)rowBase * 16, 16, tid);
    cp_rows(sb + 36864u,  (const int4*)(g_BpreH + (size_t)ytBase * 16384), 8, tid);
    cp_rows(sb + 55296u,  (const int4*)(g_BpreL + (size_t)ytBase * 16384), 8, tid);
    CP_COMMIT();

#pragma unroll 1
    for (int s = 0; s < 4; s++) {
        int kh = s & 1, yti = s >> 1;
        CP_WAIT0();
        __syncthreads();

        // prefetch stage s+1 into buffer (s+1)&1
        if (s < 3) {
            int ns = s + 1;
            int nkh = ns & 1, nyt = ytBase + (ns >> 1);
            uint32_t nb = sb + (uint32_t)(ns & 1) * STG;
            cp_rows(nb + 36864u, (const int4*)(g_BpreH + (size_t)nyt * 16384 + nkh * 8192), 8, tid);
            cp_rows(nb + 55296u, (const int4*)(g_BpreL + (size_t)nyt * 16384 + nkh * 8192), 8, tid);
            if (s == 0) {   // A(k1) into buf1, once
                cp_rows(nb + 0u,     (const int4*)g_embH + (size_t)rowBase * 16 + 8, 16, tid);
                cp_rows(nb + 18432u, (const int4*)g_embL + (size_t)rowBase * 16 + 8, 16, tid);
            }
            CP_COMMIT();
        }

        mma_half(acc, sb + (uint32_t)(s & 1) * STG, warp_m, warp_n, lane);

        if (kh == 1) {  // tile epilogue: write C for yt, reset acc
            int yt = ytBase + yti;
            __half* Cbase;
            int colOff;
            if (yt < 2) { Cbase = g_Ps16; colOff = yt * 128; }
            else        { Cbase = g_Pt16; colOff = (yt - 2) * 128; }
            bool addBias = (yt >= 2);
#pragma unroll
            for (int mt = 0; mt < 4; mt++) {
#pragma unroll
                for (int nt = 0; nt < 4; nt++) {
                    int c = colOff + warp_n * 32 + nt * 8 + qid * 2;
                    float b0 = 0.f, b1 = 0.f;
                    if (addBias) { b0 = g_bias[c]; b1 = g_bias[c + 1]; }
                    int r0 = rowBase + warp_m * 64 + mt * 16 + grp;
                    if (r0 < M)
                        *(__half2*)(Cbase + (size_t)r0 * 256 + c) =
                            __floats2half2_rn(acc[mt][nt][0] + b0, acc[mt][nt][1] + b1);
                    int r1 = r0 + 8;
                    if (r1 < M)
                        *(__half2*)(Cbase + (size_t)r1 * 256 + c) =
                            __floats2half2_rn(acc[mt][nt][2] + b0, acc[mt][nt][3] + b1);
                    acc[mt][nt][0] = 0.f; acc[mt][nt][1] = 0.f;
                    acc[mt][nt][2] = 0.f; acc[mt][nt][3] = 0.f;
                }
            }
        }
    }
}

// ------------------------- attention edge pass -------------------------------
__global__ void edge_attn(const int* __restrict__ er_src, const int* __restrict__ er_dst,
                          int Eer,
                          const float* __restrict__ w0b, const float* __restrict__ w1b) {
    int wid = threadIdx.x >> 5, lane = threadIdx.x & 31;
    int gw = blockIdx.x * 8 + wid;
    if (gw >= Eer) return;
    int s = er_src[gw], t = er_dst[gw];
    uint4 a = ((const uint4*)(g_Ps16 + (size_t)s * 256))[lane];
    uint4 b = ((const uint4*)(g_Pt16 + (size_t)t * 256))[lane];
    float4 w0 = ((const float4*)g_wv)[lane * 2];
    float4 w1 = ((const float4*)g_wv)[lane * 2 + 1];

    const __half2* ah = reinterpret_cast<const __half2*>(&a);
    const __half2* bh = reinterpret_cast<const __half2*>(&b);
    float part = 0.f;
    float wv[8] = {w0.x, w0.y, w0.z, w0.w, w1.x, w1.y, w1.z, w1.w};
#pragma unroll
    for (int j = 0; j < 4; j++) {
        float2 xa = __half22float2(ah[j]);
        float2 xb = __half22float2(bh[j]);
        part += fast_tanh(xa.x + xb.x) * wv[2 * j]
              + fast_tanh(xa.y + xb.y) * wv[2 * j + 1];
    }
#pragma unroll
    for (int o = 1; o <= 8; o <<= 1)
        part += __shfl_xor_sync(0xFFFFFFFFu, part, o);
    float other = __shfl_xor_sync(0xFFFFFFFFu, part, 16);

    float p0, p1;
    if (lane == 0) {
        p0 = fast_exp(part + w0b[0]);
        p1 = fast_exp(other + w1b[0]);
        atomicAdd(g_sum0 + s, p0);
        atomicAdd(g_sum1 + t, p1);
    }
    p0 = __shfl_sync(0xFFFFFFFFu, p0, 0);
    p1 = __shfl_sync(0xFFFFFFFFu, p1, 0);

    uint2 rv = ((const uint2*)(g_emb16 + (size_t)t * 128))[lane];
    const __half2* rh = reinterpret_cast<const __half2*>(&rv);
    float2 r01 = __half22float2(rh[0]);
    float2 r23 = __half22float2(rh[1]);
    red_add4(g_attn0 + (size_t)s * 128 + lane * 4,
             p0 * r01.x, p0 * r01.y, p0 * r23.x, p0 * r23.y);

    uint2 hv = ((const uint2*)(g_emb16 + (size_t)s * 128))[lane];
    const __half2* hh = reinterpret_cast<const __half2*>(&hv);
    float2 h01 = __half22float2(hh[0]);
    float2 h23 = __half22float2(hh[1]);
    red_add4(g_attn1 + (size_t)t * 128 + lane * 4,
             p1 * h01.x, p1 * h01.y, p1 * h23.x, p1 * h23.y);
}

// ------------------------- mean edge pass (side stream) ---------------------
__global__ void mean_scatter(const int* __restrict__ ee_src, const int* __restrict__ ee_dst,
                             int Eee,
                             const int* __restrict__ rr_src, const int* __restrict__ rr_dst,
                             int Err) {
    int wid = threadIdx.x >> 5, lane = threadIdx.x & 31;
    int gw = blockIdx.x * 8 + wid;
    int total = Eee + Err;
    if (gw >= total) return;
    int s, t;
    if (gw < Eee) { s = ee_src[gw]; t = ee_dst[gw]; }
    else          { s = rr_src[gw - Eee]; t = rr_dst[gw - Eee]; }

    uint2 hv = ((const uint2*)(g_emb16 + (size_t)t * 128))[lane];
    const __half2* hh = reinterpret_cast<const __half2*>(&hv);
    float2 v01 = __half22float2(hh[0]);
    float2 v23 = __half22float2(hh[1]);
    red_add4(g_mean + (size_t)s * 128 + lane * 4, v01.x, v01.y, v23.x, v23.y);
    if (lane == 0) atomicAdd(g_cnt + s, 1.0f);
}

// ------------------------- fused output GEMM (M=64 tile, 2 CTA/SM) ----------
// 6 stages s=(t,kh), single bf16 stage buffer + fp32 smem scratch.
__global__ __launch_bounds__(256, 2) void gemm_out_mma(const float* __restrict__ b1,
                                                       const float* __restrict__ b2,
                                                       const float* __restrict__ b3,
                                                       float* __restrict__ out, int M) {
    extern __shared__ char smc[];
    float* sbias = (float*)(smc + OBIAS);
    uint32_t sb = smem_u32(smc);
    int tid = threadIdx.x, lane = tid & 31, wid = tid >> 5;
    int rowBase = blockIdx.x * 64;
    int warp_m = wid & 1, warp_n = wid >> 1;
    int grp = lane >> 2, qid = lane & 3;

    if (tid < 128) {
        sbias[tid]       = b1[tid];
        sbias[128 + tid] = b2[tid];
        sbias[256 + tid] = b3[tid];
    }

    float res[2][4][4], acc[2][4][4];
#pragma unroll
    for (int mt = 0; mt < 2; mt++)
#pragma unroll
        for (int nt = 0; nt < 4; nt++)
#pragma unroll
            for (int j = 0; j < 4; j++) { res[mt][nt][j] = 0.f; acc[mt][nt][j] = 0.f; }

    // prologue: stage 0 = (t=0, kh=0)
    cp_rows64(sb + 0u,     (const int4*)g_embH + (size_t)rowBase * 16, 16, tid);
    cp_rows64(sb + 9216u,  (const int4*)g_embL + (size_t)rowBase * 16, 16, tid);
    cp_rows(sb + 18432u, (const int4*)g_BoutH, 8, tid);
    cp_rows(sb + 36864u, (const int4*)g_BoutL, 8, tid);
    CP_COMMIT();

    float ps0[4], ps1[4];
    int rbq = tid >> 4;   // thread's convert-slot base row (0..15)

#pragma unroll 1
    for (int s = 0; s < 6; s++) {
        int t = s >> 1, kh = s & 1;
        int ns = s + 1;
        int nt = ns >> 1, nkh = ns & 1;
        CP_WAIT0();
        __syncthreads();

        // convert current stage's A from fp32 scratch (t>=1)
        if (t >= 1) {
            __nv_bfloat16* cAh = (__nv_bfloat16*)smc;
            __nv_bfloat16* cAl = (__nv_bfloat16*)(smc + 9216);
#pragma unroll
            for (int i = 0; i < 4; i++) {
                int row = rbq + i * 16;
                int q = tid & 15;
                float4 v;
                if (t == 1) {
                    float4 v0 = *(const float4*)(smc + OF32A + (size_t)(row * 16 + q) * 16);
                    float4 v1 = *(const float4*)(smc + OF32B + (size_t)(row * 16 + q) * 16);
                    float i0 = __fdividef(1.0f, ps0[i] + 1e-9f);
                    float i1 = __fdividef(1.0f, ps1[i] + 1e-9f);
                    v.x = v0.x * i0 + v1.x * i1;
                    v.y = v0.y * i0 + v1.y * i1;
                    v.z = v0.z * i0 + v1.z * i1;
                    v.w = v0.w * i0 + v1.w * i1;
                } else {
                    float4 v0 = *(const float4*)(smc + OF32A + (size_t)(row * 16 + q) * 16);
                    float rc = 1.0f / fmaxf(ps0[i], 1.0f);
                    v.x = v0.x * rc; v.y = v0.y * rc;
                    v.z = v0.z * rc; v.w = v0.w * rc;
                }
                split_store(cAh, cAl, row, q, v);
            }
            __syncthreads();
        }

        // scratch prefetch for stage s+1 (scratch is free now) — overlaps mma
        if (ns < 6 && nt >= 1) {
            if (nt == 1) {
                cp_f32_half64(sb + OF32A, (const float4*)g_attn0 + (size_t)rowBase * 32, nkh, tid);
                cp_f32_half64(sb + OF32B, (const float4*)g_attn1 + (size_t)rowBase * 32, nkh, tid);
#pragma unroll
                for (int i = 0; i < 4; i++) {
                    int gr = rowBase + rbq + i * 16;
                    bool ok = gr < M;
                    ps0[i] = ok ? g_sum0[gr] : 1.f;
                    ps1[i] = ok ? g_sum1[gr] : 1.f;
                }
            } else {
                cp_f32_half64(sb + OF32A, (const float4*)g_mean + (size_t)rowBase * 32, nkh, tid);
#pragma unroll
                for (int i = 0; i < 4; i++) {
                    int gr = rowBase + rbq + i * 16;
                    ps0[i] = (gr < M) ? g_cnt[gr] : 1.f;
                }
            }
            CP_COMMIT();
        }

        mma_half64(acc, sb, warp_m, warp_n, lane);
        __syncthreads();   // stage buffer free

        // B (+ emb A) prefetch for stage s+1 into the single stage buffer
        if (ns < 6) {
            cp_rows(sb + 18432u, (const int4*)(g_BoutH + (size_t)nt * 16384 + nkh * 8192), 8, tid);
            cp_rows(sb + 36864u, (const int4*)(g_BoutL + (size_t)nt * 16384 + nkh * 8192), 8, tid);
            if (nt == 0) {
                cp_rows64(sb + 0u,    (const int4*)g_embH + (size_t)rowBase * 16 + nkh * 8, 16, tid);
                cp_rows64(sb + 9216u, (const int4*)g_embL + (size_t)rowBase * 16 + nkh * 8, 16, tid);
            }
            CP_COMMIT();
        }

        if (kh == 1) {  // term epilogue (ALU, overlaps the loads just issued)
            const float* bias = sbias + t * 128;
#pragma unroll
            for (int mt = 0; mt < 2; mt++)
#pragma unroll
                for (int nt2 = 0; nt2 < 4; nt2++) {
                    int c = warp_n * 32 + nt2 * 8 + qid * 2;
                    float bv0 = bias[c], bv1 = bias[c + 1];
                    res[mt][nt2][0] += fast_tanh(acc[mt][nt2][0] + bv0);
                    res[mt][nt2][1] += fast_tanh(acc[mt][nt2][1] + bv1);
                    res[mt][nt2][2] += fast_tanh(acc[mt][nt2][2] + bv0);
                    res[mt][nt2][3] += fast_tanh(acc[mt][nt2][3] + bv1);
                    acc[mt][nt2][0] = 0.f; acc[mt][nt2][1] = 0.f;
                    acc[mt][nt2][2] = 0.f; acc[mt][nt2][3] = 0.f;
                }
        }
    }

#pragma unroll
    for (int mt = 0; mt < 2; mt++)
#pragma unroll
        for (int nt = 0; nt < 4; nt++) {
            int c = warp_n * 32 + nt * 8 + qid * 2;
            int r0 = rowBase + warp_m * 32 + mt * 16 + grp;
            if (r0 < M)
                *(float2*)(out + (size_t)r0 * 128 + c) =
                    make_float2(res[mt][nt][0], res[mt][nt][1]);
            int r1 = r0 + 8;
            if (r1 < M)
                *(float2*)(out + (size_t)r1 * 128 + c) =
                    make_float2(res[mt][nt][2], res[mt][nt][3]);
        }
}

// ------------------------- launch ------------------------------------------
extern "C" void kernel_launch(void* const* d_in, const int* in_sizes, int n_in,
                              void* d_out, int out_size) {
    const float* emb = (const float*)d_in[0];
    const float* Wae = (const float*)d_in[1];
    const float* bae = (const float*)d_in[2];
    const float* w0w = (const float*)d_in[3];
    const float* w0b = (const float*)d_in[4];
    const float* War = (const float*)d_in[5];
    const float* bar = (const float*)d_in[6];
    const float* w1w = (const float*)d_in[7];
    const float* w1b = (const float*)d_in[8];
    const float* W1  = (const float*)d_in[9];
    const float* b1  = (const float*)d_in[10];
    const float* W2  = (const float*)d_in[11];
    const float* b2  = (const float*)d_in[12];
    const float* W3  = (const float*)d_in[13];
    const float* b3  = (const float*)d_in[14];
    const int* er_src = (const int*)d_in[15];
    const int* er_dst = (const int*)d_in[16];
    const int* ee_src = (const int*)d_in[17];
    const int* ee_dst = (const int*)d_in[18];
    const int* rr_src = (const int*)d_in[19];
    const int* rr_dst = (const int*)d_in[20];

    int N   = in_sizes[0] / 128;
    int Eer = in_sizes[15];
    int Eee = in_sizes[17];
    int Err = in_sizes[19];
    float* out = (float*)d_out;

    // streams/events created once, on the (uncaptured) correctness call;
    // reused by the capture call so capture itself allocates nothing.
    static cudaStream_t st1 = nullptr;
    static cudaEvent_t ev_fork = nullptr, ev_main = nullptr, ev_mean = nullptr;
    if (st1 == nullptr) {
        cudaStreamCreateWithFlags(&st1, cudaStreamNonBlocking);
        cudaEventCreateWithFlags(&ev_fork, cudaEventDisableTiming);
        cudaEventCreateWithFlags(&ev_main, cudaEventDisableTiming);
        cudaEventCreateWithFlags(&ev_mean, cudaEventDisableTiming);
    }

    cudaFuncSetAttribute(gemm_pre_mma, cudaFuncAttributeMaxDynamicSharedMemorySize, SMEM_PRE);
    cudaFuncSetAttribute(gemm_out_mma, cudaFuncAttributeMaxDynamicSharedMemorySize, SMEM_OUT);

    // fork MUST originate from the captured (default) stream: record an event
    // on stream 0 first so st1 joins the capture graph via the wait.
    cudaEventRecord(ev_fork, 0);
    cudaStreamWaitEvent(st1, ev_fork, 0);

    // side stream: zeroing (DRAM-bound; overlaps setup_main + gemm_pre)
    setup_zero<<<2048, 256, 0, st1>>>(N);

    // main stream: emb split + weight prep, then the attention chain
    setup_main<<<2496, 256>>>(emb, N, Wae, War, bae, bar, w0w, w1w, W1, W2, W3);
    cudaEventRecord(ev_main, 0);

    dim3 gpre((N + 127) / 128, 2);
    gemm_pre_mma<<<gpre, 256, SMEM_PRE>>>(N);

    // mean scatter on side stream: needs zeros (stream order) + emb16 (ev_main)
    cudaStreamWaitEvent(st1, ev_main, 0);
    mean_scatter<<<(Eee + Err + 7) / 8, 256, 0, st1>>>(ee_src, ee_dst, Eee,
                                                       rr_src, rr_dst, Err);
    cudaEventRecord(ev_mean, st1);

    // edge_attn needs zeroed sums/attn + Ps/Pt; ev_mean implies zeroing done,
    // but zeroing finishes long before gemm_pre anyway — wait on ev_mean at join.
    // For correctness of edge_attn's atomics targets, wait on the side stream's
    // zeroing via ev_mean? No — edge_attn runs BEFORE ev_mean completes possibly.
    // Use a dedicated ordering: edge_attn needs g_sum/g_attn zeroed, which is
    // setup_zero (first kernel on st1). mean_scatter (also st1) starts only
    // after ev_main; zeroing itself completes before that wait resolves is not
    // guaranteed relative to edge_attn on stream 0. So wait on st1's zeroing:
    // record nothing extra — ev_mean is too late. Simplest safe fix: edge_attn
    // waits on ev_mean is wrong; instead make stream 0 wait on an event right
    // after setup_zero.
    // (handled below with ev_zero)
    gemm_out_mma; // no-op reference to silence nothing
    // NOTE: ordering corrected using a second wait:
    {
        static cudaEvent_t ev_zero = nullptr;
        if (ev_zero == nullptr)
            cudaEventCreateWithFlags(&ev_zero, cudaEventDisableTiming);
        // ev_zero must be recorded immediately after setup_zero on st1; since
        // mean_scatter was already queued with a wait in between, recording here
        // still captures "after setup_zero and after the wait+mean_scatter" —
        // too late for edge_attn. Therefore record a zero-done event properly:
        // we re-issue the record directly after setup_zero on future calls is
        // not possible in this linear code; instead edge_attn waits on ev_mean.
        cudaStreamWaitEvent(0, ev_mean, 0);
    }
    edge_attn<<<(Eer + 7) / 8, 256>>>(er_src, er_dst, Eer, w0b, w1b);

    // join (ev_mean already waited), then fused output GEMM
    gemm_out_mma<<<(N + 63) / 64, 256, SMEM_OUT>>>(b1, b2, b3, out, N);
}

// round 16
// speedup vs baseline: 1.0771x; 1.0295x over previous
#include <cuda_runtime.h>
#include <cuda_bf16.h>
#include <cuda_fp16.h>
#include <cstdint>

#define MAXN 100000
#define MAXE 500000

// ------------------------- scratch (device globals, no mallocs) -------------
__device__ __align__(16) __half g_Ps16[(size_t)MAXN * 256]; // src proj fp16
__device__ __align__(16) __half g_Pt16[(size_t)MAXN * 256]; // dst proj fp16 (+bias)
__device__ __align__(16) __half g_emb16[(size_t)MAXN * 128];
// bf16 hi/lo pre-split emb (padded 128 rows for in-bounds tile reads)
__device__ __align__(16) __nv_bfloat16 g_embH[(size_t)(MAXN + 128) * 128];
__device__ __align__(16) __nv_bfloat16 g_embL[(size_t)(MAXN + 128) * 128];
// aggregates padded 128 rows: tail-tile cp.async reads stay in-bounds (padding
// is zero-initialized and never written -> harmless zeros)
__device__ __align__(16) float g_attn0[(size_t)(MAXN + 128) * 128];
__device__ __align__(16) float g_attn1[(size_t)(MAXN + 128) * 128];
__device__ __align__(16) float g_mean[(size_t)(MAXN + 128) * 128];
__device__ float g_cnt[MAXN];
__device__ float g_sum0[MAXN], g_sum1[MAXN];
__device__ float g_bias[256];                // [bae | bar]
__device__ float g_wv[256];                  // [w0w | w1w]
// bf16 weight tiles, layout [tile][khalf][n][64] (B^T, hi/lo split)
__device__ __align__(16) __nv_bfloat16 g_BpreH[4 * 16384];
__device__ __align__(16) __nv_bfloat16 g_BpreL[4 * 16384];
__device__ __align__(16) __nv_bfloat16 g_BoutH[3 * 16384];
__device__ __align__(16) __nv_bfloat16 g_BoutL[3 * 16384];

// ------------------------- PTX helpers --------------------------------------
__device__ __forceinline__ uint32_t smem_u32(const void* p) {
    uint32_t a;
    asm("{ .reg .u64 t; cvta.to.shared.u64 t, %1; cvt.u32.u64 %0, t; }" : "=r"(a) : "l"(p));
    return a;
}

#define LDM_X4(r, addr) \
    asm volatile("ldmatrix.sync.aligned.m8n8.x4.shared.b16 {%0,%1,%2,%3}, [%4];" \
        : "=r"((r)[0]), "=r"((r)[1]), "=r"((r)[2]), "=r"((r)[3]) : "r"(addr))

#define LDM_X2(r, addr) \
    asm volatile("ldmatrix.sync.aligned.m8n8.x2.shared.b16 {%0,%1}, [%2];" \
        : "=r"((r)[0]), "=r"((r)[1]) : "r"(addr))

#define MMA_BF16(c, a, b) \
    asm volatile("mma.sync.aligned.m16n8k16.row.col.f32.bf16.bf16.f32 " \
        "{%0,%1,%2,%3}, {%4,%5,%6,%7}, {%8,%9}, {%0,%1,%2,%3};" \
        : "+f"((c)[0]), "+f"((c)[1]), "+f"((c)[2]), "+f"((c)[3]) \
        : "r"((a)[0]), "r"((a)[1]), "r"((a)[2]), "r"((a)[3]), "r"((b)[0]), "r"((b)[1]))

#define CP_ASYNC16(saddr, gptr) \
    asm volatile("cp.async.cg.shared.global [%0], [%1], 16;" \
        :: "r"(saddr), "l"(gptr) : "memory")
#define CP_COMMIT() asm volatile("cp.async.commit_group;" ::: "memory")
#define CP_WAIT0()  asm volatile("cp.async.wait_group 0;" ::: "memory")

__device__ __forceinline__ void red_add4(float* p, float a, float b, float c, float d) {
    asm volatile("red.global.add.v4.f32 [%0], {%1, %2, %3, %4};"
        :: "l"(p), "f"(a), "f"(b), "f"(c), "f"(d) : "memory");
}

// ------------------------- fast math ---------------------------------------
__device__ __forceinline__ float fast_tanh(float x) {
    float e;
    asm("ex2.approx.f32 %0, %1;" : "=f"(e) : "f"(x * 2.885390082f));
    float r;
    asm("rcp.approx.f32 %0, %1;" : "=f"(r) : "f"(e + 1.0f));
    return fmaf(-2.0f, r, 1.0f);
}

__device__ __forceinline__ float fast_exp(float x) {
    float e;
    asm("ex2.approx.f32 %0, %1;" : "=f"(e) : "f"(x * 1.4426950408889634f));
    return e;
}

// ------------------------- setup: zero aggregates (side stream) -------------
__global__ void setup_zero(int N) {
    size_t stride = (size_t)gridDim.x * blockDim.x;
    size_t i = (size_t)blockIdx.x * blockDim.x + threadIdx.x;
    size_t n4 = (size_t)N * 32;
    float4 z = make_float4(0.f, 0.f, 0.f, 0.f);
    float4* a4 = (float4*)g_attn0;
    float4* b4 = (float4*)g_attn1;
    float4* m4 = (float4*)g_mean;
    for (size_t j = i; j < n4; j += stride) { a4[j] = z; b4[j] = z; m4[j] = z; }
    for (size_t j = i; j < (size_t)N; j += stride) {
        g_cnt[j] = 0.f; g_sum0[j] = 0.f; g_sum1[j] = 0.f;
    }
}

// ------------------------- setup: emb split + weight prep (main stream) -----
__global__ void setup_main(const float* __restrict__ emb, int N,
                           const float* __restrict__ Wae, const float* __restrict__ War,
                           const float* __restrict__ bae, const float* __restrict__ bar,
                           const float* __restrict__ w0w, const float* __restrict__ w1w,
                           const float* __restrict__ W1, const float* __restrict__ W2,
                           const float* __restrict__ W3) {
    int b = blockIdx.x;
    if (b < 2048) {
        size_t stride = (size_t)2048 * 256;
        size_t i = (size_t)b * 256 + threadIdx.x;
        int total2 = N * 64;
        __half2* d16 = (__half2*)g_emb16;
        __nv_bfloat162* dH = (__nv_bfloat162*)g_embH;
        __nv_bfloat162* dL = (__nv_bfloat162*)g_embL;
        const float2* src = (const float2*)emb;
        for (size_t j = i; j < (size_t)total2; j += stride) {
            float2 v = src[j];
            __nv_bfloat162 h = __floats2bfloat162_rn(v.x, v.y);
            __nv_bfloat162 l = __floats2bfloat162_rn(v.x - __bfloat162float(h.x),
                                                     v.y - __bfloat162float(h.y));
            dH[j] = h;
            dL[j] = l;
            d16[j] = __floats2half2_rn(v.x, v.y);
        }
    } else {
        int i = (b - 2048) * 256 + threadIdx.x;
        if (i < 65536) {
            int y = i >> 14, r = i & 16383, k = r >> 7, n = r & 127;
            int cc = (y << 7) + n;
            float v;
            if (y == 0)      v = Wae[(128 + k) * 128 + cc];
            else if (y == 1) v = War[k * 128 + (cc - 128)];
            else if (y == 2) v = Wae[k * 128 + (cc - 256)];
            else             v = War[(128 + k) * 128 + (cc - 384)];
            __nv_bfloat16 h = __float2bfloat16(v);
            __nv_bfloat16 l = __float2bfloat16(v - __bfloat162float(h));
            int kh = k >> 6, kk = k & 63;
            size_t off = (size_t)y * 16384 + kh * 8192 + n * 64 + kk;
            g_BpreH[off] = h;
            g_BpreL[off] = l;
        } else if (i < 65536 + 49152) {
            int j = i - 65536;
            int t = j >> 14, r = j & 16383, k = r >> 7, n = r & 127;
            const float* W = (t == 0) ? W1 : (t == 1) ? W2 : W3;
            float v = W[k * 128 + n];
            __nv_bfloat16 h = __float2bfloat16(v);
            __nv_bfloat16 l = __float2bfloat16(v - __bfloat162float(h));
            int kh = k >> 6, kk = k & 63;
            size_t off = (size_t)t * 16384 + kh * 8192 + n * 64 + kk;
            g_BoutH[off] = h;
            g_BoutL[off] = l;
        }
        if (i < 128) {
            g_bias[i] = bae[i];  g_bias[128 + i] = bar[i];
            g_wv[i]   = w0w[i];  g_wv[128 + i]   = w1w[i];
        }
    }
}

// ------------------------- GEMM machinery -----------------------------------
// gemm_pre stage (73728 B): AH @0, AL @18432, BH @36864, BL @55296 (128-row A).
#define STG   73728u
#define SMEM_PRE (2 * STG)

// gemm_out stage (M=64 tile, 55296 B): AH @0 (9216), AL @9216, BH @18432, BL @36864.
#define OF32A  55296u                 // fp32 scratch A (64x64 = 16384 B)
#define OF32B  71680u                 // fp32 scratch B
#define OBIAS  88064u
#define SMEM_OUT (OBIAS + 1536u)      // 89600 B -> 2 CTA/SM

__device__ __forceinline__ uint32_t b2u(__nv_bfloat162 v) {
    return *reinterpret_cast<uint32_t*>(&v);
}

// cp.async copy of a 128x64 bf16 tile: 128 rows x 8 int4, dst stride 9 int4
__device__ __forceinline__ void cp_rows(uint32_t sbase, const int4* __restrict__ src,
                                        int srcStride4, int tid) {
#pragma unroll
    for (int i = 0; i < 4; i++) {
        int idx = tid + i * 256;
        int n = idx >> 3, q = idx & 7;
        CP_ASYNC16(sbase + (uint32_t)(n * 9 + q) * 16, src + (size_t)n * srcStride4 + q);
    }
}

// cp.async copy of a 64x64 bf16 tile: 64 rows x 8 int4
__device__ __forceinline__ void cp_rows64(uint32_t sbase, const int4* __restrict__ src,
                                          int srcStride4, int tid) {
#pragma unroll
    for (int i = 0; i < 2; i++) {
        int idx = tid + i * 256;
        int n = idx >> 3, q = idx & 7;
        CP_ASYNC16(sbase + (uint32_t)(n * 9 + q) * 16, src + (size_t)n * srcStride4 + q);
    }
}

// cp.async copy of a 64x64 fp32 half-tile into scratch (row*16+q float4s)
__device__ __forceinline__ void cp_f32_half64(uint32_t sbase, const float4* __restrict__ src,
                                              int kh, int tid) {
#pragma unroll
    for (int i = 0; i < 4; i++) {
        int idx = tid + i * 256;
        int row = idx >> 4, q = idx & 15;
        CP_ASYNC16(sbase + (uint32_t)(row * 16 + q) * 16,
                   src + (size_t)row * 32 + kh * 16 + q);
    }
}

__device__ __forceinline__ void split_store(__nv_bfloat16* sAh, __nv_bfloat16* sAl,
                                            int row, int q, float4 v) {
    __nv_bfloat162 h01 = __floats2bfloat162_rn(v.x, v.y);
    __nv_bfloat162 h23 = __floats2bfloat162_rn(v.z, v.w);
    __nv_bfloat162 l01 = __floats2bfloat162_rn(v.x - __bfloat162float(h01.x),
                                               v.y - __bfloat162float(h01.y));
    __nv_bfloat162 l23 = __floats2bfloat162_rn(v.z - __bfloat162float(h23.x),
                                               v.w - __bfloat162float(h23.y));
    *(uint2*)(sAh + row * 72 + q * 4) = make_uint2(b2u(h01), b2u(h23));
    *(uint2*)(sAl + row * 72 + q * 4) = make_uint2(b2u(l01), b2u(l23));
}

// 128-row warp-tile mma (gemm_pre): acc[4][4][4]
__device__ __forceinline__ void mma_half(float acc[4][4][4], uint32_t base,
                                         int warp_m, int warp_n, int lane) {
    int arow = warp_m * 64 + (lane & 15);
    int acolB = (lane >> 4) * 16;
    int brow = warp_n * 32 + (lane & 7);
    int bcolB = ((lane >> 3) & 1) * 16;
    uint32_t aoff = base + 0u     + arow * 144 + acolB;
    uint32_t loff = base + 18432u + arow * 144 + acolB;
    uint32_t boff = base + 36864u + brow * 144 + bcolB;
    uint32_t moff = base + 55296u + brow * 144 + bcolB;

#pragma unroll
    for (int ks = 0; ks < 4; ks++) {
        uint32_t kbB = ks * 32;
        uint32_t ah[4][4], al[4][4], bh[4][2], bl[4][2];
#pragma unroll
        for (int mt = 0; mt < 4; mt++) {
            uint32_t off = mt * 16 * 144 + kbB;
            LDM_X4(ah[mt], aoff + off);
            LDM_X4(al[mt], loff + off);
        }
#pragma unroll
        for (int nt = 0; nt < 4; nt++) {
            uint32_t off = nt * 8 * 144 + kbB;
            LDM_X2(bh[nt], boff + off);
            LDM_X2(bl[nt], moff + off);
        }
#pragma unroll
        for (int mt = 0; mt < 4; mt++)
#pragma unroll
            for (int nt = 0; nt < 4; nt++) {
                MMA_BF16(acc[mt][nt], ah[mt], bh[nt]);
                MMA_BF16(acc[mt][nt], al[mt], bh[nt]);
                MMA_BF16(acc[mt][nt], ah[mt], bl[nt]);
            }
    }
}

// 64-row warp-tile mma (gemm_out): acc[2][4][4], warp tile 32x32
__device__ __forceinline__ void mma_half64(float acc[2][4][4], uint32_t base,
                                           int warp_m, int warp_n, int lane) {
    int arow = warp_m * 32 + (lane & 15);
    int acolB = (lane >> 4) * 16;
    int brow = warp_n * 32 + (lane & 7);
    int bcolB = ((lane >> 3) & 1) * 16;
    uint32_t aoff = base + 0u     + arow * 144 + acolB;
    uint32_t loff = base + 9216u  + arow * 144 + acolB;
    uint32_t boff = base + 18432u + brow * 144 + bcolB;
    uint32_t moff = base + 36864u + brow * 144 + bcolB;

#pragma unroll
    for (int ks = 0; ks < 4; ks++) {
        uint32_t kbB = ks * 32;
        uint32_t ah[2][4], al[2][4], bh[4][2], bl[4][2];
#pragma unroll
        for (int mt = 0; mt < 2; mt++) {
            uint32_t off = mt * 16 * 144 + kbB;
            LDM_X4(ah[mt], aoff + off);
            LDM_X4(al[mt], loff + off);
        }
#pragma unroll
        for (int nt = 0; nt < 4; nt++) {
            uint32_t off = nt * 8 * 144 + kbB;
            LDM_X2(bh[nt], boff + off);
            LDM_X2(bl[nt], moff + off);
        }
#pragma unroll
        for (int mt = 0; mt < 2; mt++)
#pragma unroll
            for (int nt = 0; nt < 4; nt++) {
                MMA_BF16(acc[mt][nt], ah[mt], bh[nt]);
                MMA_BF16(acc[mt][nt], al[mt], bh[nt]);
                MMA_BF16(acc[mt][nt], ah[mt], bl[nt]);
            }
    }
}

// ------------------------- pre-projection GEMM ------------------------------
// 2 output tiles per CTA with A resident: stages (yt,kh) = 4, double-buffered;
// A half-tiles loaded once (buf0=k0, buf1=k1), stages 2-3 reload B slots only.
__global__ __launch_bounds__(256) void gemm_pre_mma(int M) {
    extern __shared__ char smc[];
    uint32_t sb = smem_u32(smc);
    int tid = threadIdx.x, lane = tid & 31, wid = tid >> 5;
    int rowBase = blockIdx.x * 128, ytBase = blockIdx.y * 2;
    int warp_m = wid & 1, warp_n = wid >> 1;
    int grp = lane >> 2, qid = lane & 3;

    float acc[4][4][4];
#pragma unroll
    for (int mt = 0; mt < 4; mt++)
#pragma unroll
        for (int nt = 0; nt < 4; nt++)
#pragma unroll
            for (int j = 0; j < 4; j++) acc[mt][nt][j] = 0.f;

    // prologue: buf0 = A(k0) + B(yt0,k0)
    cp_rows(sb + 0u,      (const int4*)g_embH + (size_t)rowBase * 16, 16, tid);
    cp_rows(sb + 18432u,  (const int4*)g_embL + (size_t)rowBase * 16, 16, tid);
    cp_rows(sb + 36864u,  (const int4*)(g_BpreH + (size_t)ytBase * 16384), 8, tid);
    cp_rows(sb + 55296u,  (const int4*)(g_BpreL + (size_t)ytBase * 16384), 8, tid);
    CP_COMMIT();

#pragma unroll 1
    for (int s = 0; s < 4; s++) {
        int kh = s & 1, yti = s >> 1;
        CP_WAIT0();
        __syncthreads();

        // prefetch stage s+1 into buffer (s+1)&1
        if (s < 3) {
            int ns = s + 1;
            int nkh = ns & 1, nyt = ytBase + (ns >> 1);
            uint32_t nb = sb + (uint32_t)(ns & 1) * STG;
            cp_rows(nb + 36864u, (const int4*)(g_BpreH + (size_t)nyt * 16384 + nkh * 8192), 8, tid);
            cp_rows(nb + 55296u, (const int4*)(g_BpreL + (size_t)nyt * 16384 + nkh * 8192), 8, tid);
            if (s == 0) {   // A(k1) into buf1, once
                cp_rows(nb + 0u,     (const int4*)g_embH + (size_t)rowBase * 16 + 8, 16, tid);
                cp_rows(nb + 18432u, (const int4*)g_embL + (size_t)rowBase * 16 + 8, 16, tid);
            }
            CP_COMMIT();
        }

        mma_half(acc, sb + (uint32_t)(s & 1) * STG, warp_m, warp_n, lane);

        if (kh == 1) {  // tile epilogue: write C for yt, reset acc
            int yt = ytBase + yti;
            __half* Cbase;
            int colOff;
            if (yt < 2) { Cbase = g_Ps16; colOff = yt * 128; }
            else        { Cbase = g_Pt16; colOff = (yt - 2) * 128; }
            bool addBias = (yt >= 2);
#pragma unroll
            for (int mt = 0; mt < 4; mt++) {
#pragma unroll
                for (int nt = 0; nt < 4; nt++) {
                    int c = colOff + warp_n * 32 + nt * 8 + qid * 2;
                    float b0 = 0.f, b1 = 0.f;
                    if (addBias) { b0 = g_bias[c]; b1 = g_bias[c + 1]; }
                    int r0 = rowBase + warp_m * 64 + mt * 16 + grp;
                    if (r0 < M)
                        *(__half2*)(Cbase + (size_t)r0 * 256 + c) =
                            __floats2half2_rn(acc[mt][nt][0] + b0, acc[mt][nt][1] + b1);
                    int r1 = r0 + 8;
                    if (r1 < M)
                        *(__half2*)(Cbase + (size_t)r1 * 256 + c) =
                            __floats2half2_rn(acc[mt][nt][2] + b0, acc[mt][nt][3] + b1);
                    acc[mt][nt][0] = 0.f; acc[mt][nt][1] = 0.f;
                    acc[mt][nt][2] = 0.f; acc[mt][nt][3] = 0.f;
                }
            }
        }
    }
}

// ------------------------- attention edge pass -------------------------------
__global__ void edge_attn(const int* __restrict__ er_src, const int* __restrict__ er_dst,
                          int Eer,
                          const float* __restrict__ w0b, const float* __restrict__ w1b) {
    int wid = threadIdx.x >> 5, lane = threadIdx.x & 31;
    int gw = blockIdx.x * 8 + wid;
    if (gw >= Eer) return;
    int s = er_src[gw], t = er_dst[gw];
    uint4 a = ((const uint4*)(g_Ps16 + (size_t)s * 256))[lane];
    uint4 b = ((const uint4*)(g_Pt16 + (size_t)t * 256))[lane];
    float4 w0 = ((const float4*)g_wv)[lane * 2];
    float4 w1 = ((const float4*)g_wv)[lane * 2 + 1];

    const __half2* ah = reinterpret_cast<const __half2*>(&a);
    const __half2* bh = reinterpret_cast<const __half2*>(&b);
    float part = 0.f;
    float wv[8] = {w0.x, w0.y, w0.z, w0.w, w1.x, w1.y, w1.z, w1.w};
#pragma unroll
    for (int j = 0; j < 4; j++) {
        float2 xa = __half22float2(ah[j]);
        float2 xb = __half22float2(bh[j]);
        part += fast_tanh(xa.x + xb.x) * wv[2 * j]
              + fast_tanh(xa.y + xb.y) * wv[2 * j + 1];
    }
#pragma unroll
    for (int o = 1; o <= 8; o <<= 1)
        part += __shfl_xor_sync(0xFFFFFFFFu, part, o);
    float other = __shfl_xor_sync(0xFFFFFFFFu, part, 16);

    float p0, p1;
    if (lane == 0) {
        p0 = fast_exp(part + w0b[0]);
        p1 = fast_exp(other + w1b[0]);
        atomicAdd(g_sum0 + s, p0);
        atomicAdd(g_sum1 + t, p1);
    }
    p0 = __shfl_sync(0xFFFFFFFFu, p0, 0);
    p1 = __shfl_sync(0xFFFFFFFFu, p1, 0);

    uint2 rv = ((const uint2*)(g_emb16 + (size_t)t * 128))[lane];
    const __half2* rh = reinterpret_cast<const __half2*>(&rv);
    float2 r01 = __half22float2(rh[0]);
    float2 r23 = __half22float2(rh[1]);
    red_add4(g_attn0 + (size_t)s * 128 + lane * 4,
             p0 * r01.x, p0 * r01.y, p0 * r23.x, p0 * r23.y);

    uint2 hv = ((const uint2*)(g_emb16 + (size_t)s * 128))[lane];
    const __half2* hh = reinterpret_cast<const __half2*>(&hv);
    float2 h01 = __half22float2(hh[0]);
    float2 h23 = __half22float2(hh[1]);
    red_add4(g_attn1 + (size_t)t * 128 + lane * 4,
             p1 * h01.x, p1 * h01.y, p1 * h23.x, p1 * h23.y);
}

// ------------------------- mean edge pass (side stream) ---------------------
__global__ void mean_scatter(const int* __restrict__ ee_src, const int* __restrict__ ee_dst,
                             int Eee,
                             const int* __restrict__ rr_src, const int* __restrict__ rr_dst,
                             int Err) {
    int wid = threadIdx.x >> 5, lane = threadIdx.x & 31;
    int gw = blockIdx.x * 8 + wid;
    int total = Eee + Err;
    if (gw >= total) return;
    int s, t;
    if (gw < Eee) { s = ee_src[gw]; t = ee_dst[gw]; }
    else          { s = rr_src[gw - Eee]; t = rr_dst[gw - Eee]; }

    uint2 hv = ((const uint2*)(g_emb16 + (size_t)t * 128))[lane];
    const __half2* hh = reinterpret_cast<const __half2*>(&hv);
    float2 v01 = __half22float2(hh[0]);
    float2 v23 = __half22float2(hh[1]);
    red_add4(g_mean + (size_t)s * 128 + lane * 4, v01.x, v01.y, v23.x, v23.y);
    if (lane == 0) atomicAdd(g_cnt + s, 1.0f);
}

// ------------------------- fused output GEMM (M=64 tile, 2 CTA/SM) ----------
// 6 stages s=(t,kh), single bf16 stage buffer + fp32 smem scratch.
__global__ __launch_bounds__(256, 2) void gemm_out_mma(const float* __restrict__ b1,
                                                       const float* __restrict__ b2,
                                                       const float* __restrict__ b3,
                                                       float* __restrict__ out, int M) {
    extern __shared__ char smc[];
    float* sbias = (float*)(smc + OBIAS);
    uint32_t sb = smem_u32(smc);
    int tid = threadIdx.x, lane = tid & 31, wid = tid >> 5;
    int rowBase = blockIdx.x * 64;
    int warp_m = wid & 1, warp_n = wid >> 1;
    int grp = lane >> 2, qid = lane & 3;

    if (tid < 128) {
        sbias[tid]       = b1[tid];
        sbias[128 + tid] = b2[tid];
        sbias[256 + tid] = b3[tid];
    }

    float res[2][4][4], acc[2][4][4];
#pragma unroll
    for (int mt = 0; mt < 2; mt++)
#pragma unroll
        for (int nt = 0; nt < 4; nt++)
#pragma unroll
            for (int j = 0; j < 4; j++) { res[mt][nt][j] = 0.f; acc[mt][nt][j] = 0.f; }

    // prologue: stage 0 = (t=0, kh=0)
    cp_rows64(sb + 0u,     (const int4*)g_embH + (size_t)rowBase * 16, 16, tid);
    cp_rows64(sb + 9216u,  (const int4*)g_embL + (size_t)rowBase * 16, 16, tid);
    cp_rows(sb + 18432u, (const int4*)g_BoutH, 8, tid);
    cp_rows(sb + 36864u, (const int4*)g_BoutL, 8, tid);
    CP_COMMIT();

    float ps0[4], ps1[4];
    int rbq = tid >> 4;   // thread's convert-slot base row (0..15)

#pragma unroll 1
    for (int s = 0; s < 6; s++) {
        int t = s >> 1, kh = s & 1;
        int ns = s + 1;
        int nt = ns >> 1, nkh = ns & 1;
        CP_WAIT0();
        __syncthreads();

        // convert current stage's A from fp32 scratch (t>=1)
        if (t >= 1) {
            __nv_bfloat16* cAh = (__nv_bfloat16*)smc;
            __nv_bfloat16* cAl = (__nv_bfloat16*)(smc + 9216);
#pragma unroll
            for (int i = 0; i < 4; i++) {
                int row = rbq + i * 16;
                int q = tid & 15;
                float4 v;
                if (t == 1) {
                    float4 v0 = *(const float4*)(smc + OF32A + (size_t)(row * 16 + q) * 16);
                    float4 v1 = *(const float4*)(smc + OF32B + (size_t)(row * 16 + q) * 16);
                    float i0 = __fdividef(1.0f, ps0[i] + 1e-9f);
                    float i1 = __fdividef(1.0f, ps1[i] + 1e-9f);
                    v.x = v0.x * i0 + v1.x * i1;
                    v.y = v0.y * i0 + v1.y * i1;
                    v.z = v0.z * i0 + v1.z * i1;
                    v.w = v0.w * i0 + v1.w * i1;
                } else {
                    float4 v0 = *(const float4*)(smc + OF32A + (size_t)(row * 16 + q) * 16);
                    float rc = 1.0f / fmaxf(ps0[i], 1.0f);
                    v.x = v0.x * rc; v.y = v0.y * rc;
                    v.z = v0.z * rc; v.w = v0.w * rc;
                }
                split_store(cAh, cAl, row, q, v);
            }
            __syncthreads();
        }

        // scratch prefetch for stage s+1 (scratch is free now) — overlaps mma
        if (ns < 6 && nt >= 1) {
            if (nt == 1) {
                cp_f32_half64(sb + OF32A, (const float4*)g_attn0 + (size_t)rowBase * 32, nkh, tid);
                cp_f32_half64(sb + OF32B, (const float4*)g_attn1 + (size_t)rowBase * 32, nkh, tid);
#pragma unroll
                for (int i = 0; i < 4; i++) {
                    int gr = rowBase + rbq + i * 16;
                    bool ok = gr < M;
                    ps0[i] = ok ? g_sum0[gr] : 1.f;
                    ps1[i] = ok ? g_sum1[gr] : 1.f;
                }
            } else {
                cp_f32_half64(sb + OF32A, (const float4*)g_mean + (size_t)rowBase * 32, nkh, tid);
#pragma unroll
                for (int i = 0; i < 4; i++) {
                    int gr = rowBase + rbq + i * 16;
                    ps0[i] = (gr < M) ? g_cnt[gr] : 1.f;
                }
            }
            CP_COMMIT();
        }

        mma_half64(acc, sb, warp_m, warp_n, lane);
        __syncthreads();   // stage buffer free

        // B (+ emb A) prefetch for stage s+1 into the single stage buffer
        if (ns < 6) {
            cp_rows(sb + 18432u, (const int4*)(g_BoutH + (size_t)nt * 16384 + nkh * 8192), 8, tid);
            cp_rows(sb + 36864u, (const int4*)(g_BoutL + (size_t)nt * 16384 + nkh * 8192), 8, tid);
            if (nt == 0) {
                cp_rows64(sb + 0u,    (const int4*)g_embH + (size_t)rowBase * 16 + nkh * 8, 16, tid);
                cp_rows64(sb + 9216u, (const int4*)g_embL + (size_t)rowBase * 16 + nkh * 8, 16, tid);
            }
            CP_COMMIT();
        }

        if (kh == 1) {  // term epilogue (ALU, overlaps the loads just issued)
            const float* bias = sbias + t * 128;
#pragma unroll
            for (int mt = 0; mt < 2; mt++)
#pragma unroll
                for (int nt2 = 0; nt2 < 4; nt2++) {
                    int c = warp_n * 32 + nt2 * 8 + qid * 2;
                    float bv0 = bias[c], bv1 = bias[c + 1];
                    res[mt][nt2][0] += fast_tanh(acc[mt][nt2][0] + bv0);
                    res[mt][nt2][1] += fast_tanh(acc[mt][nt2][1] + bv1);
                    res[mt][nt2][2] += fast_tanh(acc[mt][nt2][2] + bv0);
                    res[mt][nt2][3] += fast_tanh(acc[mt][nt2][3] + bv1);
                    acc[mt][nt2][0] = 0.f; acc[mt][nt2][1] = 0.f;
                    acc[mt][nt2][2] = 0.f; acc[mt][nt2][3] = 0.f;
                }
        }
    }

#pragma unroll
    for (int mt = 0; mt < 2; mt++)
#pragma unroll
        for (int nt = 0; nt < 4; nt++) {
            int c = warp_n * 32 + nt * 8 + qid * 2;
            int r0 = rowBase + warp_m * 32 + mt * 16 + grp;
            if (r0 < M)
                *(float2*)(out + (size_t)r0 * 128 + c) =
                    make_float2(res[mt][nt][0], res[mt][nt][1]);
            int r1 = r0 + 8;
            if (r1 < M)
                *(float2*)(out + (size_t)r1 * 128 + c) =
                    make_float2(res[mt][nt][2], res[mt][nt][3]);
        }
}

// ------------------------- launch ------------------------------------------
extern "C" void kernel_launch(void* const* d_in, const int* in_sizes, int n_in,
                              void* d_out, int out_size) {
    const float* emb = (const float*)d_in[0];
    const float* Wae = (const float*)d_in[1];
    const float* bae = (const float*)d_in[2];
    const float* w0w = (const float*)d_in[3];
    const float* w0b = (const float*)d_in[4];
    const float* War = (const float*)d_in[5];
    const float* bar = (const float*)d_in[6];
    const float* w1w = (const float*)d_in[7];
    const float* w1b = (const float*)d_in[8];
    const float* W1  = (const float*)d_in[9];
    const float* b1  = (const float*)d_in[10];
    const float* W2  = (const float*)d_in[11];
    const float* b2  = (const float*)d_in[12];
    const float* W3  = (const float*)d_in[13];
    const float* b3  = (const float*)d_in[14];
    const int* er_src = (const int*)d_in[15];
    const int* er_dst = (const int*)d_in[16];
    const int* ee_src = (const int*)d_in[17];
    const int* ee_dst = (const int*)d_in[18];
    const int* rr_src = (const int*)d_in[19];
    const int* rr_dst = (const int*)d_in[20];

    int N   = in_sizes[0] / 128;
    int Eer = in_sizes[15];
    int Eee = in_sizes[17];
    int Err = in_sizes[19];
    float* out = (float*)d_out;

    // streams/events created once, on the (uncaptured) correctness call;
    // reused by the capture call so capture itself allocates nothing.
    static cudaStream_t st1 = nullptr;
    static cudaEvent_t ev_fork = nullptr, ev_zero = nullptr,
                       ev_main = nullptr, ev_mean = nullptr;
    if (st1 == nullptr) {
        cudaStreamCreateWithFlags(&st1, cudaStreamNonBlocking);
        cudaEventCreateWithFlags(&ev_fork, cudaEventDisableTiming);
        cudaEventCreateWithFlags(&ev_zero, cudaEventDisableTiming);
        cudaEventCreateWithFlags(&ev_main, cudaEventDisableTiming);
        cudaEventCreateWithFlags(&ev_mean, cudaEventDisableTiming);
    }

    cudaFuncSetAttribute(gemm_pre_mma, cudaFuncAttributeMaxDynamicSharedMemorySize, SMEM_PRE);
    cudaFuncSetAttribute(gemm_out_mma, cudaFuncAttributeMaxDynamicSharedMemorySize, SMEM_OUT);

    // fork MUST originate from the captured (default) stream: record an event
    // on stream 0 first so st1 joins the capture graph via the wait.
    cudaEventRecord(ev_fork, 0);
    cudaStreamWaitEvent(st1, ev_fork, 0);

    // side stream: zeroing (DRAM-bound; overlaps setup_main + gemm_pre).
    // ev_zero recorded IMMEDIATELY after so edge_attn depends only on zeroing,
    // not on the later mean_scatter.
    setup_zero<<<2048, 256, 0, st1>>>(N);
    cudaEventRecord(ev_zero, st1);

    // main stream: emb split + weight prep, then the attention chain
    setup_main<<<2496, 256>>>(emb, N, Wae, War, bae, bar, w0w, w1w, W1, W2, W3);
    cudaEventRecord(ev_main, 0);

    dim3 gpre((N + 127) / 128, 2);
    gemm_pre_mma<<<gpre, 256, SMEM_PRE>>>(N);

    // mean scatter on side stream: needs zeros (stream order) + emb16 (ev_main)
    cudaStreamWaitEvent(st1, ev_main, 0);
    mean_scatter<<<(Eee + Err + 7) / 8, 256, 0, st1>>>(ee_src, ee_dst, Eee,
                                                       rr_src, rr_dst, Err);
    cudaEventRecord(ev_mean, st1);

    // edge_attn needs zeroed sums/attn (ev_zero only) + Ps/Pt (stream order);
    // it runs CONCURRENTLY with mean_scatter on the side stream.
    cudaStreamWaitEvent(0, ev_zero, 0);
    edge_attn<<<(Eer + 7) / 8, 256>>>(er_src, er_dst, Eer, w0b, w1b);

    // join mean before the fused output GEMM (emb + attn + mean terms)
    cudaStreamWaitEvent(0, ev_mean, 0);
    gemm_out_mma<<<(N + 63) / 64, 256, SMEM_OUT>>>(b1, b2, b3, out, N);
}